// round 1
// baseline (speedup 1.0000x reference)
#include <cuda_runtime.h>
#include <math.h>
#include <stdint.h>

// ---------------- problem constants ----------------
// B=64, TOK=20, D=512, H=8, L=4, S=512, HD=64, ODIM=32
// effective batch G = 128 sequences (64 samples x 2 halves)
// rows M = G*S = 65536

#define NROW 65536          // 128*512
#define DIM  512
#define NBH  1024           // 128*8

// ---------------- scratch (device globals; no allocation allowed) ----------
__device__ float g_t  [NROW * DIM];          // activations t           (134 MB)
__device__ float g_qkv[NROW * 1536];         // qkv                     (402 MB)
__device__ float g_sc [(size_t)NBH * 512 * 512]; // scores / attn      (1073 MB)
__device__ float g_o  [NROW * DIM];          // attn out / ffn out      (134 MB)
__device__ float g_mid[NROW * 2048];         // ffn hidden              (536 MB)
__device__ float g_h  [64 * 32768];          // encoder output h        (8 MB)

// ---------------- input projection: t = x.reshape(.,512,20) @ in_W + in_b --
__global__ void k_inproj(const float* __restrict__ x, const float* __restrict__ W,
                         const float* __restrict__ bias, float* __restrict__ t)
{
    int row = blockIdx.x;                       // 0..65535
    int d   = blockIdx.y * 256 + threadIdx.x;   // 0..511
    int g = row >> 9, s = row & 511;
    int b = g >> 1, half = g & 1;
    const float* xp = x + (size_t)b * 20480 + (size_t)half * 10240 + (size_t)s * 20;
    float acc = bias[d];
#pragma unroll
    for (int k = 0; k < 20; k++) acc += xp[k] * W[k * 512 + d];
    t[(size_t)row * 512 + d] = acc;
}

// ---------------- generic SGEMM: C = act(A(MxK) @ B(KxN) + bias) -----------
// BM=BN=128, BK=8, 256 threads, 8x8 microtile. Requires M%128==0, N%128==0, K%8==0.
__global__ __launch_bounds__(256)
void k_sgemm(int M, int N, int K,
             const float* __restrict__ A, const float* __restrict__ B,
             const float* __restrict__ bias, float* __restrict__ C, int relu)
{
    __shared__ float As[8][128];
    __shared__ float Bs[8][128];
    int bx = blockIdx.x, by = blockIdx.y;
    int tid = threadIdx.x;
    int tx = tid & 15, ty = tid >> 4;
    int aRow = tid >> 1, aCol = (tid & 1) << 2;
    int bRow = tid >> 5, bCol = (tid & 31) << 2;
    const float* Ap = A + (size_t)by * 128 * K;
    const float* Bp = B + (size_t)bx * 128;

    float acc[8][8];
#pragma unroll
    for (int i = 0; i < 8; i++)
#pragma unroll
        for (int j = 0; j < 8; j++) acc[i][j] = 0.f;

    for (int k0 = 0; k0 < K; k0 += 8) {
        float4 a4 = *(const float4*)(Ap + (size_t)aRow * K + k0 + aCol);
        As[aCol + 0][aRow] = a4.x;
        As[aCol + 1][aRow] = a4.y;
        As[aCol + 2][aRow] = a4.z;
        As[aCol + 3][aRow] = a4.w;
        float4 b4 = *(const float4*)(Bp + (size_t)(k0 + bRow) * N + bCol);
        *(float4*)&Bs[bRow][bCol] = b4;
        __syncthreads();
#pragma unroll
        for (int kk = 0; kk < 8; kk++) {
            float4 a0 = *(const float4*)&As[kk][ty * 8];
            float4 a1 = *(const float4*)&As[kk][ty * 8 + 4];
            float4 b0 = *(const float4*)&Bs[kk][tx * 8];
            float4 b1 = *(const float4*)&Bs[kk][tx * 8 + 4];
            float ar[8] = {a0.x, a0.y, a0.z, a0.w, a1.x, a1.y, a1.z, a1.w};
            float br[8] = {b0.x, b0.y, b0.z, b0.w, b1.x, b1.y, b1.z, b1.w};
#pragma unroll
            for (int i = 0; i < 8; i++)
#pragma unroll
                for (int j = 0; j < 8; j++) acc[i][j] += ar[i] * br[j];
        }
        __syncthreads();
    }

    int cRow0 = by * 128 + ty * 8;
    int cCol0 = bx * 128 + tx * 8;
#pragma unroll
    for (int i = 0; i < 8; i++) {
        size_t off = (size_t)(cRow0 + i) * N + cCol0;
#pragma unroll
        for (int j = 0; j < 8; j++) {
            float v = acc[i][j] + bias[cCol0 + j];
            if (relu) v = fmaxf(v, 0.f);
            C[off + j] = v;
        }
    }
}

// ---------------- scores: sc[bh,i,j] = scale*q.k + alibi ------------------
__global__ __launch_bounds__(256)
void k_scores(const float* __restrict__ qkv, float* __restrict__ sc)
{
    int bh = blockIdx.z; int g = bh >> 3, h = bh & 7;
    int i0 = blockIdx.y * 64, j0 = blockIdx.x * 64;
    __shared__ float Qs[64][64]; // [d][i]
    __shared__ float Ks[64][64]; // [d][j]
    int tid = threadIdx.x;
    const size_t base = (size_t)g * 512 * 1536 + h * 64;

    for (int t = tid; t < 1024; t += 256) {
        int r = t >> 4;
        int dv = (t & 15) << 2;
        float4 q4 = *(const float4*)(qkv + base + (size_t)(i0 + r) * 1536 + dv);
        Qs[dv + 0][r] = q4.x; Qs[dv + 1][r] = q4.y; Qs[dv + 2][r] = q4.z; Qs[dv + 3][r] = q4.w;
        float4 k4 = *(const float4*)(qkv + base + 512 + (size_t)(j0 + r) * 1536 + dv);
        Ks[dv + 0][r] = k4.x; Ks[dv + 1][r] = k4.y; Ks[dv + 2][r] = k4.z; Ks[dv + 3][r] = k4.w;
    }
    __syncthreads();

    int ti = tid >> 4, tj = tid & 15;
    float acc[4][4] = {};
#pragma unroll 8
    for (int d = 0; d < 64; d++) {
        float4 q4 = *(const float4*)&Qs[d][ti * 4];
        float4 k4 = *(const float4*)&Ks[d][tj * 4];
        float qa[4] = {q4.x, q4.y, q4.z, q4.w};
        float ka[4] = {k4.x, k4.y, k4.z, k4.w};
#pragma unroll
        for (int a = 0; a < 4; a++)
#pragma unroll
            for (int b2 = 0; b2 < 4; b2++) acc[a][b2] += qa[a] * ka[b2];
    }
    float slope = 1.0f / (float)(1 << (h >> 2));
    float* out = sc + ((size_t)bh * 512 + i0) * 512 + j0;
#pragma unroll
    for (int a = 0; a < 4; a++) {
        int ig = i0 + ti * 4 + a;
#pragma unroll
        for (int b2 = 0; b2 < 4; b2++) {
            int jg = j0 + tj * 4 + b2;
            out[(size_t)(ti * 4 + a) * 512 + tj * 4 + b2] =
                acc[a][b2] * 0.125f - slope * fabsf((float)(ig - jg));
        }
    }
}

// ---------------- rowwise softmax over 512, in place ----------------------
__global__ void k_softmax(float* __restrict__ sc)
{
    size_t row = blockIdx.x;
    float* p = sc + row * 512;
    int tid = threadIdx.x; // 128
    float v[4];
    float mx = -1e30f;
#pragma unroll
    for (int i = 0; i < 4; i++) { v[i] = p[tid + i * 128]; mx = fmaxf(mx, v[i]); }
    __shared__ float red[128];
    red[tid] = mx; __syncthreads();
    for (int s = 64; s > 0; s >>= 1) { if (tid < s) red[tid] = fmaxf(red[tid], red[tid + s]); __syncthreads(); }
    mx = red[0]; __syncthreads();
    float sum = 0.f;
#pragma unroll
    for (int i = 0; i < 4; i++) { v[i] = expf(v[i] - mx); sum += v[i]; }
    red[tid] = sum; __syncthreads();
    for (int s = 64; s > 0; s >>= 1) { if (tid < s) red[tid] += red[tid + s]; __syncthreads(); }
    float inv = 1.0f / red[0];
#pragma unroll
    for (int i = 0; i < 4; i++) p[tid + i * 128] = v[i] * inv;
}

// ---------------- PV: o[g,i,h*64+d] = sum_j attn[bh,i,j] * v[g,j,h,d] -----
__global__ __launch_bounds__(256)
void k_pv(const float* __restrict__ sc, const float* __restrict__ qkv,
          float* __restrict__ o)
{
    int bh = blockIdx.y; int g = bh >> 3, h = bh & 7;
    int i0 = blockIdx.x * 64;
    __shared__ float Ps[32][64]; // [k][i]
    __shared__ float Vs[32][64]; // [k][d]
    int tid = threadIdx.x;
    int ti = tid >> 4, tj = tid & 15;
    float acc[4][4] = {};
    const float* prow = sc + ((size_t)bh * 512 + i0) * 512;
    const size_t vbase = (size_t)g * 512 * 1536 + 1024 + h * 64;

    for (int k0 = 0; k0 < 512; k0 += 32) {
        for (int t = tid; t < 512; t += 256) {
            int r = t >> 3;
            int kv = (t & 7) << 2;
            float4 p4 = *(const float4*)(prow + (size_t)r * 512 + k0 + kv);
            Ps[kv + 0][r] = p4.x; Ps[kv + 1][r] = p4.y; Ps[kv + 2][r] = p4.z; Ps[kv + 3][r] = p4.w;
        }
        for (int t = tid; t < 512; t += 256) {
            int kk = t >> 4;
            int dv = (t & 15) << 2;
            *(float4*)&Vs[kk][dv] = *(const float4*)(qkv + vbase + (size_t)(k0 + kk) * 1536 + dv);
        }
        __syncthreads();
#pragma unroll 8
        for (int k = 0; k < 32; k++) {
            float4 p4 = *(const float4*)&Ps[k][ti * 4];
            float4 v4 = *(const float4*)&Vs[k][tj * 4];
            float pa[4] = {p4.x, p4.y, p4.z, p4.w};
            float va[4] = {v4.x, v4.y, v4.z, v4.w};
#pragma unroll
            for (int a = 0; a < 4; a++)
#pragma unroll
                for (int b2 = 0; b2 < 4; b2++) acc[a][b2] += pa[a] * va[b2];
        }
        __syncthreads();
    }
    float* op = o + ((size_t)g * 512 + i0) * 512 + h * 64;
#pragma unroll
    for (int a = 0; a < 4; a++) {
        int ir = ti * 4 + a;
#pragma unroll
        for (int b2 = 0; b2 < 4; b2++)
            op[(size_t)ir * 512 + tj * 4 + b2] = acc[a][b2];
    }
}

// ---------------- fused residual-add + LayerNorm (in place on res ok) -----
__global__ void k_addln(const float* __restrict__ res, const float* __restrict__ add,
                        const float* __restrict__ gam, const float* __restrict__ bet,
                        float* __restrict__ out)
{
    size_t row = blockIdx.x;
    int tid = threadIdx.x; // 128
    float v[4];
    float s = 0.f;
#pragma unroll
    for (int i = 0; i < 4; i++) {
        int c = tid + i * 128;
        v[i] = res[row * 512 + c] + add[row * 512 + c];
        s += v[i];
    }
    __shared__ float red[128];
    red[tid] = s; __syncthreads();
    for (int st = 64; st > 0; st >>= 1) { if (tid < st) red[tid] += red[tid + st]; __syncthreads(); }
    float mean = red[0] * (1.f / 512.f);
    __syncthreads();
    float s2 = 0.f;
#pragma unroll
    for (int i = 0; i < 4; i++) { float d = v[i] - mean; s2 += d * d; }
    red[tid] = s2; __syncthreads();
    for (int st = 64; st > 0; st >>= 1) { if (tid < st) red[tid] += red[tid + st]; __syncthreads(); }
    float inv = 1.0f / sqrtf(red[0] * (1.f / 512.f) + 1e-5f);
#pragma unroll
    for (int i = 0; i < 4; i++) {
        int c = tid + i * 128;
        out[row * 512 + c] = (v[i] - mean) * inv * gam[c] + bet[c];
    }
}

// ---------------- out proj: h[b, half*16384 + s*32 + c] -------------------
__global__ __launch_bounds__(256)
void k_outproj(const float* __restrict__ t, const float* __restrict__ W,
               const float* __restrict__ bias, float* __restrict__ hout)
{
    __shared__ float Ws[128][32];
    __shared__ float As[8][128];
    int tid = threadIdx.x;
    int r = tid >> 5, c = tid & 31;
    int row0 = blockIdx.x * 8;
    float acc = bias[c];
    for (int k0 = 0; k0 < 512; k0 += 128) {
        for (int tt = tid; tt < 4096; tt += 256)
            Ws[tt >> 5][tt & 31] = W[(size_t)(k0 + (tt >> 5)) * 32 + (tt & 31)];
        for (int tt = tid; tt < 1024; tt += 256)
            As[tt >> 7][tt & 127] = t[(size_t)(row0 + (tt >> 7)) * 512 + k0 + (tt & 127)];
        __syncthreads();
#pragma unroll 16
        for (int k = 0; k < 128; k++) acc += As[r][k] * Ws[k][c];
        __syncthreads();
    }
    int row = row0 + r;
    int g = row >> 9, s = row & 511;
    int b = g >> 1, half = g & 1;
    hout[(size_t)b * 32768 + half * 16384 + s * 32 + c] = acc;
}

// ---------------- MLP head: 32768 -> 256 -> 128 -> 1 ----------------------
__global__ __launch_bounds__(256)
void k_head(const float* __restrict__ h,
            const float* __restrict__ d1W, const float* __restrict__ d1b,
            const float* __restrict__ bn1g, const float* __restrict__ bn1b,
            const float* __restrict__ bn1m, const float* __restrict__ bn1v,
            const float* __restrict__ d2W, const float* __restrict__ d2b,
            const float* __restrict__ bn2g, const float* __restrict__ bn2b,
            const float* __restrict__ bn2m, const float* __restrict__ bn2v,
            const float* __restrict__ finW, const float* __restrict__ finb,
            float* __restrict__ out)
{
    int b = blockIdx.x;
    int tid = threadIdx.x; // 256
    __shared__ float hs[2048];
    float acc = d1b[tid];
    const float* hrow = h + (size_t)b * 32768;
    for (int k0 = 0; k0 < 32768; k0 += 2048) {
        for (int t = tid; t < 2048; t += 256) hs[t] = hrow[k0 + t];
        __syncthreads();
#pragma unroll 8
        for (int k = 0; k < 2048; k++) acc += hs[k] * d1W[(size_t)(k0 + k) * 256 + tid];
        __syncthreads();
    }
    float z = fmaxf(acc, 0.f);
    __shared__ float s1[256];
    s1[tid] = (z - bn1m[tid]) / sqrtf(bn1v[tid] + 1e-5f) * bn1g[tid] + bn1b[tid];
    __syncthreads();
    __shared__ float s2[128];
    if (tid < 128) {
        float a2 = d2b[tid];
#pragma unroll 8
        for (int k = 0; k < 256; k++) a2 += s1[k] * d2W[k * 128 + tid];
        float z2 = fmaxf(a2, 0.f);
        s2[tid] = (z2 - bn2m[tid]) / sqrtf(bn2v[tid] + 1e-5f) * bn2g[tid] + bn2b[tid];
    }
    __syncthreads();
    __shared__ float red[128];
    if (tid < 128) red[tid] = s2[tid] * finW[tid];
    __syncthreads();
    for (int st = 64; st > 0; st >>= 1) {
        if (tid < st) red[tid] += red[tid + st];
        __syncthreads();
    }
    if (tid == 0) out[b] = red[0] + finb[0];
}

// ---------------- launch ---------------------------------------------------
extern "C" void kernel_launch(void* const* d_in, const int* in_sizes, int n_in,
                              void* d_out, int out_size)
{
    const float* x      = (const float*)d_in[0];
    const float* in_W   = (const float*)d_in[1];
    const float* in_b   = (const float*)d_in[2];
    const float* qkv_W  = (const float*)d_in[3];
    const float* qkv_b  = (const float*)d_in[4];
    const float* ln1_g  = (const float*)d_in[5];
    const float* ln1_b  = (const float*)d_in[6];
    const float* ffn_W1 = (const float*)d_in[7];
    const float* ffn_b1 = (const float*)d_in[8];
    const float* ffn_W2 = (const float*)d_in[9];
    const float* ffn_b2 = (const float*)d_in[10];
    const float* ln2_g  = (const float*)d_in[11];
    const float* ln2_b  = (const float*)d_in[12];
    const float* out_W  = (const float*)d_in[13];
    const float* out_b  = (const float*)d_in[14];
    const float* d1_W   = (const float*)d_in[15];
    const float* d1_b   = (const float*)d_in[16];
    const float* bn1_g  = (const float*)d_in[17];
    const float* bn1_b  = (const float*)d_in[18];
    const float* bn1_m  = (const float*)d_in[19];
    const float* bn1_v  = (const float*)d_in[20];
    const float* d2_W   = (const float*)d_in[21];
    const float* d2_b   = (const float*)d_in[22];
    const float* bn2_g  = (const float*)d_in[23];
    const float* bn2_b  = (const float*)d_in[24];
    const float* bn2_m  = (const float*)d_in[25];
    const float* bn2_v  = (const float*)d_in[26];
    const float* fin_W  = (const float*)d_in[27];
    const float* fin_b  = (const float*)d_in[28];
    float* out = (float*)d_out;

    float *t, *qkv, *sc, *o, *mid, *h;
    cudaGetSymbolAddress((void**)&t,   g_t);
    cudaGetSymbolAddress((void**)&qkv, g_qkv);
    cudaGetSymbolAddress((void**)&sc,  g_sc);
    cudaGetSymbolAddress((void**)&o,   g_o);
    cudaGetSymbolAddress((void**)&mid, g_mid);
    cudaGetSymbolAddress((void**)&h,   g_h);

    k_inproj<<<dim3(65536, 2), 256>>>(x, in_W, in_b, t);

    for (int l = 0; l < 4; l++) {
        k_sgemm<<<dim3(12, 512), 256>>>(NROW, 1536, 512,
                                        t, qkv_W + (size_t)l * 512 * 1536,
                                        qkv_b + l * 1536, qkv, 0);
        k_scores<<<dim3(8, 8, NBH), 256>>>(qkv, sc);
        k_softmax<<<(unsigned)(NBH * 512), 128>>>(sc);
        k_pv<<<dim3(8, NBH), 256>>>(sc, qkv, o);
        k_addln<<<NROW, 128>>>(t, o, ln1_g + l * 512, ln1_b + l * 512, t);
        k_sgemm<<<dim3(16, 512), 256>>>(NROW, 2048, 512,
                                        t, ffn_W1 + (size_t)l * 512 * 2048,
                                        ffn_b1 + l * 2048, mid, 1);
        k_sgemm<<<dim3(4, 512), 256>>>(NROW, 512, 2048,
                                       mid, ffn_W2 + (size_t)l * 2048 * 512,
                                       ffn_b2 + l * 512, o, 0);
        k_addln<<<NROW, 128>>>(t, o, ln2_g + l * 512, ln2_b + l * 512, t);
    }

    k_outproj<<<8192, 256>>>(t, out_W, out_b, h);
    k_head<<<64, 256>>>(h, d1_W, d1_b, bn1_g, bn1_b, bn1_m, bn1_v,
                        d2_W, d2_b, bn2_g, bn2_b, bn2_m, bn2_v,
                        fin_W, fin_b, out);
}

// round 2
// speedup vs baseline: 1.2936x; 1.2936x over previous
#include <cuda_runtime.h>
#include <mma.h>
#include <math.h>
#include <stdint.h>

using namespace nvcuda;

// ---------------- problem constants ----------------
// B=64, TOK=20, D=512, H=8, L=4, S=512, HD=64, ODIM=32
#define NROW 65536          // 128*512
#define NBH  1024           // 128*8

// ---------------- scratch (device globals) ---------------------------------
__device__ float g_t  [NROW * 512];
__device__ float g_qkv[NROW * 1536];
__device__ float g_sc [(size_t)NBH * 512 * 512];
__device__ float g_o  [NROW * 512];
__device__ float g_mid[NROW * 2048];
__device__ float g_h  [64 * 32768];

// ---------------- input projection ----------------------------------------
__global__ void k_inproj(const float* __restrict__ x, const float* __restrict__ W,
                         const float* __restrict__ bias, float* __restrict__ t)
{
    int row = blockIdx.x;
    int d   = blockIdx.y * 256 + threadIdx.x;
    int g = row >> 9, s = row & 511;
    int b = g >> 1, half = g & 1;
    const float* xp = x + (size_t)b * 20480 + (size_t)half * 10240 + (size_t)s * 20;
    float acc = bias[d];
#pragma unroll
    for (int k = 0; k < 20; k++) acc += xp[k] * W[k * 512 + d];
    t[(size_t)row * 512 + d] = acc;
}

// ---------------- TF32 wmma SGEMM: C = act(A(MxK) @ B(KxN) + bias) ---------
// BM=128, BN=128, BK=32. 256 threads = 8 warps (2x4), warp tile 64x32.
__global__ __launch_bounds__(256)
void k_gemm_tf32(int M, int N, int K,
                 const float* __restrict__ A, const float* __restrict__ B,
                 const float* __restrict__ bias, float* __restrict__ C, int relu)
{
    __shared__ float As[128][36];   // [m][k] tf32-rounded
    __shared__ float Bs[32][132];   // [k][n]
    __shared__ float stage[8][16][20];

    int tid = threadIdx.x;
    int wid = tid >> 5, lane = tid & 31;
    int warpRow = wid >> 2;         // 0..1  -> 64-row strip
    int warpCol = wid & 3;          // 0..3  -> 32-col strip
    int row0 = blockIdx.y * 128;
    int col0 = blockIdx.x * 128;

    wmma::fragment<wmma::accumulator, 16, 16, 8, float> c[4][2];
#pragma unroll
    for (int m = 0; m < 4; m++)
#pragma unroll
        for (int n = 0; n < 2; n++) wmma::fill_fragment(c[m][n], 0.0f);

    for (int k0 = 0; k0 < K; k0 += 32) {
        // load A tile 128x32
#pragma unroll
        for (int t = 0; t < 4; t++) {
            int idx = tid + t * 256;
            int r = idx >> 3, c4 = (idx & 7) << 2;
            float4 a4 = *(const float4*)(A + (size_t)(row0 + r) * K + k0 + c4);
            As[r][c4 + 0] = wmma::__float_to_tf32(a4.x);
            As[r][c4 + 1] = wmma::__float_to_tf32(a4.y);
            As[r][c4 + 2] = wmma::__float_to_tf32(a4.z);
            As[r][c4 + 3] = wmma::__float_to_tf32(a4.w);
        }
        // load B tile 32x128
#pragma unroll
        for (int t = 0; t < 4; t++) {
            int idx = tid + t * 256;
            int r = idx >> 5, c4 = (idx & 31) << 2;
            float4 b4 = *(const float4*)(B + (size_t)(k0 + r) * N + col0 + c4);
            Bs[r][c4 + 0] = wmma::__float_to_tf32(b4.x);
            Bs[r][c4 + 1] = wmma::__float_to_tf32(b4.y);
            Bs[r][c4 + 2] = wmma::__float_to_tf32(b4.z);
            Bs[r][c4 + 3] = wmma::__float_to_tf32(b4.w);
        }
        __syncthreads();

#pragma unroll
        for (int kk = 0; kk < 4; kk++) {
            wmma::fragment<wmma::matrix_a, 16, 16, 8, wmma::precision::tf32, wmma::row_major> af[4];
            wmma::fragment<wmma::matrix_b, 16, 16, 8, wmma::precision::tf32, wmma::row_major> bf[2];
#pragma unroll
            for (int m = 0; m < 4; m++)
                wmma::load_matrix_sync(af[m], &As[warpRow * 64 + m * 16][kk * 8], 36);
#pragma unroll
            for (int n = 0; n < 2; n++)
                wmma::load_matrix_sync(bf[n], &Bs[kk * 8][warpCol * 32 + n * 16], 132);
#pragma unroll
            for (int m = 0; m < 4; m++)
#pragma unroll
                for (int n = 0; n < 2; n++)
                    wmma::mma_sync(c[m][n], af[m], bf[n], c[m][n]);
        }
        __syncthreads();
    }

    // epilogue: bias (+relu) via per-warp staging
#pragma unroll
    for (int m = 0; m < 4; m++)
#pragma unroll
        for (int n = 0; n < 2; n++) {
            wmma::store_matrix_sync(&stage[wid][0][0], c[m][n], 20, wmma::mem_row_major);
            __syncwarp();
            int rowBase = row0 + warpRow * 64 + m * 16;
            int colBase = col0 + warpCol * 32 + n * 16;
#pragma unroll
            for (int p = 0; p < 2; p++) {
                int fid = lane + p * 32;          // 0..63
                int r = fid >> 2, c4 = (fid & 3) << 2;
                float4 v;
                v.x = stage[wid][r][c4 + 0];
                v.y = stage[wid][r][c4 + 1];
                v.z = stage[wid][r][c4 + 2];
                v.w = stage[wid][r][c4 + 3];
                float4 b4 = *(const float4*)(bias + colBase + c4);
                v.x += b4.x; v.y += b4.y; v.z += b4.z; v.w += b4.w;
                if (relu) {
                    v.x = fmaxf(v.x, 0.f); v.y = fmaxf(v.y, 0.f);
                    v.z = fmaxf(v.z, 0.f); v.w = fmaxf(v.w, 0.f);
                }
                *(float4*)(C + (size_t)(rowBase + r) * N + colBase + c4) = v;
            }
            __syncwarp();
        }
}

// ---------------- scores (tf32 wmma): sc = scale*QK^T + alibi --------------
// block = 128 thr (4 warps), each block: 64(i) x 64(j) tile of one bh.
__global__ __launch_bounds__(128)
void k_scores(const float* __restrict__ qkv, float* __restrict__ sc)
{
    __shared__ float Qs[64][68];   // [i][d]
    __shared__ float Ks[64][68];   // [j][d]
    __shared__ float stage[4][16][20];

    int bh = blockIdx.z; int g = bh >> 3, h = bh & 7;
    int i0 = blockIdx.y * 64, j0 = blockIdx.x * 64;
    int tid = threadIdx.x, wid = tid >> 5, lane = tid & 31;
    const size_t base = (size_t)g * 512 * 1536 + h * 64;

#pragma unroll
    for (int t = 0; t < 8; t++) {
        int idx = tid + t * 128;
        int r = idx >> 4, c4 = (idx & 15) << 2;
        float4 q4 = *(const float4*)(qkv + base + (size_t)(i0 + r) * 1536 + c4);
        Qs[r][c4 + 0] = wmma::__float_to_tf32(q4.x);
        Qs[r][c4 + 1] = wmma::__float_to_tf32(q4.y);
        Qs[r][c4 + 2] = wmma::__float_to_tf32(q4.z);
        Qs[r][c4 + 3] = wmma::__float_to_tf32(q4.w);
        float4 k4 = *(const float4*)(qkv + base + 512 + (size_t)(j0 + r) * 1536 + c4);
        Ks[r][c4 + 0] = wmma::__float_to_tf32(k4.x);
        Ks[r][c4 + 1] = wmma::__float_to_tf32(k4.y);
        Ks[r][c4 + 2] = wmma::__float_to_tf32(k4.z);
        Ks[r][c4 + 3] = wmma::__float_to_tf32(k4.w);
    }
    __syncthreads();

    wmma::fragment<wmma::accumulator, 16, 16, 8, float> c[4];
#pragma unroll
    for (int n = 0; n < 4; n++) wmma::fill_fragment(c[n], 0.0f);

#pragma unroll
    for (int kk = 0; kk < 8; kk++) {
        wmma::fragment<wmma::matrix_a, 16, 16, 8, wmma::precision::tf32, wmma::row_major> af;
        wmma::load_matrix_sync(af, &Qs[wid * 16][kk * 8], 68);
#pragma unroll
        for (int n = 0; n < 4; n++) {
            wmma::fragment<wmma::matrix_b, 16, 16, 8, wmma::precision::tf32, wmma::col_major> bf;
            wmma::load_matrix_sync(bf, &Ks[n * 16][kk * 8], 68);
            wmma::mma_sync(c[n], af, bf, c[n]);
        }
    }

    float slope = 1.0f / (float)(1 << (h >> 2));
    float* out = sc + ((size_t)bh * 512) * 512;
#pragma unroll
    for (int n = 0; n < 4; n++) {
        wmma::store_matrix_sync(&stage[wid][0][0], c[n], 20, wmma::mem_row_major);
        __syncwarp();
#pragma unroll
        for (int p = 0; p < 2; p++) {
            int fid = lane + p * 32;
            int r = fid >> 2, c4 = (fid & 3) << 2;
            int ig = i0 + wid * 16 + r;
            int jg = j0 + n * 16 + c4;
            float4 v;
            v.x = stage[wid][r][c4 + 0] * 0.125f - slope * fabsf((float)(ig - jg));
            v.y = stage[wid][r][c4 + 1] * 0.125f - slope * fabsf((float)(ig - jg - 1));
            v.z = stage[wid][r][c4 + 2] * 0.125f - slope * fabsf((float)(ig - jg - 2));
            v.w = stage[wid][r][c4 + 3] * 0.125f - slope * fabsf((float)(ig - jg - 3));
            *(float4*)(out + (size_t)ig * 512 + jg) = v;
        }
        __syncwarp();
    }
}

// ---------------- rowwise softmax over 512 (float4 vectorized) -------------
__global__ void k_softmax(float* __restrict__ sc)
{
    size_t row = blockIdx.x;
    float4* p = (float4*)(sc + row * 512);
    int tid = threadIdx.x;                // 128
    float4 v = p[tid];
    float mx = fmaxf(fmaxf(v.x, v.y), fmaxf(v.z, v.w));
#pragma unroll
    for (int s = 16; s > 0; s >>= 1) mx = fmaxf(mx, __shfl_xor_sync(0xffffffff, mx, s));
    __shared__ float red[4];
    if ((tid & 31) == 0) red[tid >> 5] = mx;
    __syncthreads();
    mx = fmaxf(fmaxf(red[0], red[1]), fmaxf(red[2], red[3]));
    v.x = expf(v.x - mx); v.y = expf(v.y - mx);
    v.z = expf(v.z - mx); v.w = expf(v.w - mx);
    float sum = v.x + v.y + v.z + v.w;
#pragma unroll
    for (int s = 16; s > 0; s >>= 1) sum += __shfl_xor_sync(0xffffffff, sum, s);
    __shared__ float red2[4];
    if ((tid & 31) == 0) red2[tid >> 5] = sum;
    __syncthreads();
    float inv = 1.0f / (red2[0] + red2[1] + red2[2] + red2[3]);
    v.x *= inv; v.y *= inv; v.z *= inv; v.w *= inv;
    p[tid] = v;
}

// ---------------- PV (tf32 wmma): o = attn @ V ------------------------------
// block = 128 thr (4 warps), each block: 64(i) x 64(d) for one bh.
__global__ __launch_bounds__(128)
void k_pv(const float* __restrict__ sc, const float* __restrict__ qkv,
          float* __restrict__ o)
{
    __shared__ float Ps[64][36];   // [i][k-chunk]
    __shared__ float Vs[32][68];   // [k][d]

    int bh = blockIdx.y; int g = bh >> 3, h = bh & 7;
    int i0 = blockIdx.x * 64;
    int tid = threadIdx.x, wid = tid >> 5;
    const float* prow = sc + ((size_t)bh * 512 + i0) * 512;
    const size_t vbase = (size_t)g * 512 * 1536 + 1024 + h * 64;

    wmma::fragment<wmma::accumulator, 16, 16, 8, float> c[4];
#pragma unroll
    for (int n = 0; n < 4; n++) wmma::fill_fragment(c[n], 0.0f);

    for (int k0 = 0; k0 < 512; k0 += 32) {
#pragma unroll
        for (int t = 0; t < 4; t++) {
            int idx = tid + t * 128;
            int r = idx >> 3, c4 = (idx & 7) << 2;
            float4 p4 = *(const float4*)(prow + (size_t)r * 512 + k0 + c4);
            Ps[r][c4 + 0] = wmma::__float_to_tf32(p4.x);
            Ps[r][c4 + 1] = wmma::__float_to_tf32(p4.y);
            Ps[r][c4 + 2] = wmma::__float_to_tf32(p4.z);
            Ps[r][c4 + 3] = wmma::__float_to_tf32(p4.w);
        }
#pragma unroll
        for (int t = 0; t < 4; t++) {
            int idx = tid + t * 128;
            int r = idx >> 4, c4 = (idx & 15) << 2;
            float4 v4 = *(const float4*)(qkv + vbase + (size_t)(k0 + r) * 1536 + c4);
            Vs[r][c4 + 0] = wmma::__float_to_tf32(v4.x);
            Vs[r][c4 + 1] = wmma::__float_to_tf32(v4.y);
            Vs[r][c4 + 2] = wmma::__float_to_tf32(v4.z);
            Vs[r][c4 + 3] = wmma::__float_to_tf32(v4.w);
        }
        __syncthreads();
#pragma unroll
        for (int kk = 0; kk < 4; kk++) {
            wmma::fragment<wmma::matrix_a, 16, 16, 8, wmma::precision::tf32, wmma::row_major> af;
            wmma::load_matrix_sync(af, &Ps[wid * 16][kk * 8], 36);
#pragma unroll
            for (int n = 0; n < 4; n++) {
                wmma::fragment<wmma::matrix_b, 16, 16, 8, wmma::precision::tf32, wmma::row_major> bf;
                wmma::load_matrix_sync(bf, &Vs[kk * 8][n * 16], 68);
                wmma::mma_sync(c[n], af, bf, c[n]);
            }
        }
        __syncthreads();
    }

    float* op = o + ((size_t)g * 512 + i0 + wid * 16) * 512 + h * 64;
#pragma unroll
    for (int n = 0; n < 4; n++)
        wmma::store_matrix_sync(op + n * 16, c[n], 512, wmma::mem_row_major);
}

// ---------------- fused residual-add + LayerNorm ---------------------------
__global__ void k_addln(const float* __restrict__ res, const float* __restrict__ add,
                        const float* __restrict__ gam, const float* __restrict__ bet,
                        float* __restrict__ out)
{
    size_t row = blockIdx.x;
    int tid = threadIdx.x; // 128
    float v[4];
    float s = 0.f;
#pragma unroll
    for (int i = 0; i < 4; i++) {
        int c = tid + i * 128;
        v[i] = res[row * 512 + c] + add[row * 512 + c];
        s += v[i];
    }
    __shared__ float red[128];
    red[tid] = s; __syncthreads();
    for (int st = 64; st > 0; st >>= 1) { if (tid < st) red[tid] += red[tid + st]; __syncthreads(); }
    float mean = red[0] * (1.f / 512.f);
    __syncthreads();
    float s2 = 0.f;
#pragma unroll
    for (int i = 0; i < 4; i++) { float d = v[i] - mean; s2 += d * d; }
    red[tid] = s2; __syncthreads();
    for (int st = 64; st > 0; st >>= 1) { if (tid < st) red[tid] += red[tid + st]; __syncthreads(); }
    float inv = 1.0f / sqrtf(red[0] * (1.f / 512.f) + 1e-5f);
#pragma unroll
    for (int i = 0; i < 4; i++) {
        int c = tid + i * 128;
        out[row * 512 + c] = (v[i] - mean) * inv * gam[c] + bet[c];
    }
}

// ---------------- out proj --------------------------------------------------
__global__ __launch_bounds__(256)
void k_outproj(const float* __restrict__ t, const float* __restrict__ W,
               const float* __restrict__ bias, float* __restrict__ hout)
{
    __shared__ float Ws[128][32];
    __shared__ float As[8][128];
    int tid = threadIdx.x;
    int r = tid >> 5, c = tid & 31;
    int row0 = blockIdx.x * 8;
    float acc = bias[c];
    for (int k0 = 0; k0 < 512; k0 += 128) {
        for (int tt = tid; tt < 4096; tt += 256)
            Ws[tt >> 5][tt & 31] = W[(size_t)(k0 + (tt >> 5)) * 32 + (tt & 31)];
        for (int tt = tid; tt < 1024; tt += 256)
            As[tt >> 7][tt & 127] = t[(size_t)(row0 + (tt >> 7)) * 512 + k0 + (tt & 127)];
        __syncthreads();
#pragma unroll 16
        for (int k = 0; k < 128; k++) acc += As[r][k] * Ws[k][c];
        __syncthreads();
    }
    int row = row0 + r;
    int g = row >> 9, s = row & 511;
    int b = g >> 1, half = g & 1;
    hout[(size_t)b * 32768 + half * 16384 + s * 32 + c] = acc;
}

// ---------------- MLP head --------------------------------------------------
__global__ __launch_bounds__(256)
void k_head(const float* __restrict__ h,
            const float* __restrict__ d1W, const float* __restrict__ d1b,
            const float* __restrict__ bn1g, const float* __restrict__ bn1b,
            const float* __restrict__ bn1m, const float* __restrict__ bn1v,
            const float* __restrict__ d2W, const float* __restrict__ d2b,
            const float* __restrict__ bn2g, const float* __restrict__ bn2b,
            const float* __restrict__ bn2m, const float* __restrict__ bn2v,
            const float* __restrict__ finW, const float* __restrict__ finb,
            float* __restrict__ out)
{
    int b = blockIdx.x;
    int tid = threadIdx.x; // 256
    __shared__ float hs[2048];
    float acc = d1b[tid];
    const float* hrow = h + (size_t)b * 32768;
    for (int k0 = 0; k0 < 32768; k0 += 2048) {
        for (int t = tid; t < 2048; t += 256) hs[t] = hrow[k0 + t];
        __syncthreads();
#pragma unroll 8
        for (int k = 0; k < 2048; k++) acc += hs[k] * d1W[(size_t)(k0 + k) * 256 + tid];
        __syncthreads();
    }
    float z = fmaxf(acc, 0.f);
    __shared__ float s1[256];
    s1[tid] = (z - bn1m[tid]) / sqrtf(bn1v[tid] + 1e-5f) * bn1g[tid] + bn1b[tid];
    __syncthreads();
    __shared__ float s2[128];
    if (tid < 128) {
        float a2 = d2b[tid];
#pragma unroll 8
        for (int k = 0; k < 256; k++) a2 += s1[k] * d2W[k * 128 + tid];
        float z2 = fmaxf(a2, 0.f);
        s2[tid] = (z2 - bn2m[tid]) / sqrtf(bn2v[tid] + 1e-5f) * bn2g[tid] + bn2b[tid];
    }
    __syncthreads();
    __shared__ float red[128];
    if (tid < 128) red[tid] = s2[tid] * finW[tid];
    __syncthreads();
    for (int st = 64; st > 0; st >>= 1) {
        if (tid < st) red[tid] += red[tid + st];
        __syncthreads();
    }
    if (tid == 0) out[b] = red[0] + finb[0];
}

// ---------------- launch ----------------------------------------------------
extern "C" void kernel_launch(void* const* d_in, const int* in_sizes, int n_in,
                              void* d_out, int out_size)
{
    const float* x      = (const float*)d_in[0];
    const float* in_W   = (const float*)d_in[1];
    const float* in_b   = (const float*)d_in[2];
    const float* qkv_W  = (const float*)d_in[3];
    const float* qkv_b  = (const float*)d_in[4];
    const float* ln1_g  = (const float*)d_in[5];
    const float* ln1_b  = (const float*)d_in[6];
    const float* ffn_W1 = (const float*)d_in[7];
    const float* ffn_b1 = (const float*)d_in[8];
    const float* ffn_W2 = (const float*)d_in[9];
    const float* ffn_b2 = (const float*)d_in[10];
    const float* ln2_g  = (const float*)d_in[11];
    const float* ln2_b  = (const float*)d_in[12];
    const float* out_W  = (const float*)d_in[13];
    const float* out_b  = (const float*)d_in[14];
    const float* d1_W   = (const float*)d_in[15];
    const float* d1_b   = (const float*)d_in[16];
    const float* bn1_g  = (const float*)d_in[17];
    const float* bn1_b  = (const float*)d_in[18];
    const float* bn1_m  = (const float*)d_in[19];
    const float* bn1_v  = (const float*)d_in[20];
    const float* d2_W   = (const float*)d_in[21];
    const float* d2_b   = (const float*)d_in[22];
    const float* bn2_g  = (const float*)d_in[23];
    const float* bn2_b  = (const float*)d_in[24];
    const float* bn2_m  = (const float*)d_in[25];
    const float* bn2_v  = (const float*)d_in[26];
    const float* fin_W  = (const float*)d_in[27];
    const float* fin_b  = (const float*)d_in[28];
    float* out = (float*)d_out;

    float *t, *qkv, *sc, *o, *mid, *h;
    cudaGetSymbolAddress((void**)&t,   g_t);
    cudaGetSymbolAddress((void**)&qkv, g_qkv);
    cudaGetSymbolAddress((void**)&sc,  g_sc);
    cudaGetSymbolAddress((void**)&o,   g_o);
    cudaGetSymbolAddress((void**)&mid, g_mid);
    cudaGetSymbolAddress((void**)&h,   g_h);

    k_inproj<<<dim3(65536, 2), 256>>>(x, in_W, in_b, t);

    for (int l = 0; l < 4; l++) {
        k_gemm_tf32<<<dim3(12, 512), 256>>>(NROW, 1536, 512,
                                            t, qkv_W + (size_t)l * 512 * 1536,
                                            qkv_b + l * 1536, qkv, 0);
        k_scores<<<dim3(8, 8, NBH), 128>>>(qkv, sc);
        k_softmax<<<(unsigned)(NBH * 512), 128>>>(sc);
        k_pv<<<dim3(8, NBH), 128>>>(sc, qkv, o);
        k_addln<<<NROW, 128>>>(t, o, ln1_g + l * 512, ln1_b + l * 512, t);
        k_gemm_tf32<<<dim3(16, 512), 256>>>(NROW, 2048, 512,
                                            t, ffn_W1 + (size_t)l * 512 * 2048,
                                            ffn_b1 + l * 2048, mid, 1);
        k_gemm_tf32<<<dim3(4, 512), 256>>>(NROW, 512, 2048,
                                           mid, ffn_W2 + (size_t)l * 2048 * 512,
                                           ffn_b2 + l * 512, o, 0);
        k_addln<<<NROW, 128>>>(t, o, ln2_g + l * 512, ln2_b + l * 512, t);
    }

    k_outproj<<<8192, 256>>>(t, out_W, out_b, h);
    k_head<<<64, 256>>>(h, d1_W, d1_b, bn1_g, bn1_b, bn1_m, bn1_v,
                        d2_W, d2_b, bn2_g, bn2_b, bn2_m, bn2_v,
                        fin_W, fin_b, out);
}

// round 3
// speedup vs baseline: 4.0636x; 3.1414x over previous
#include <cuda_runtime.h>
#include <cuda_fp16.h>
#include <mma.h>
#include <math.h>
#include <stdint.h>

using namespace nvcuda;

// ---------------- problem constants ----------------
// B=64, TOK=20, D=512, H=8, L=4, S=512, HD=64, ODIM=32
#define NROW 65536          // 128*512
#define NBH  1024           // 128*8

// ---------------- scratch (device globals) ---------------------------------
__device__ float  g_t   [NROW * 512];                 // fp32 residual stream
__device__ __half g_t16 [NROW * 512];                 // fp16 shadow of t
__device__ __half g_qkv [NROW * 1536];                // fp16 qkv
__device__ float  g_sc  [(size_t)NBH * 512 * 512];    // fp32 scores/probs
__device__ float  g_o   [NROW * 512];                 // fp32 attn/ffn out
__device__ __half g_mid [NROW * 2048];                // fp16 ffn hidden
__device__ float  g_h   [64 * 32768];
__device__ __half g_w1  [4 * 512 * 1536];             // qkv_W fp16
__device__ __half g_w2  [4 * 512 * 2048];             // ffn_W1 fp16
__device__ __half g_w3  [4 * 2048 * 512];             // ffn_W2 fp16

// ---------------- cp.async helpers -----------------------------------------
__device__ __forceinline__ void cp_async16(void* smem_dst, const void* gmem_src) {
    unsigned s = (unsigned)__cvta_generic_to_shared(smem_dst);
    asm volatile("cp.async.cg.shared.global [%0], [%1], 16;\n" :: "r"(s), "l"(gmem_src));
}
__device__ __forceinline__ void cp_commit() { asm volatile("cp.async.commit_group;\n" ::: "memory"); }
__device__ __forceinline__ void cp_wait1()  { asm volatile("cp.async.wait_group 1;\n" ::: "memory"); }
__device__ __forceinline__ void cp_wait0()  { asm volatile("cp.async.wait_group 0;\n" ::: "memory"); }

// ---------------- fp32 -> fp16 convert -------------------------------------
__global__ void k_cvt16(const float* __restrict__ src, __half* __restrict__ dst, int n)
{
    int i = blockIdx.x * 256 + threadIdx.x;
    if (i < n) dst[i] = __float2half(src[i]);
}

// ---------------- input projection (writes fp32 + fp16) --------------------
__global__ void k_inproj(const float* __restrict__ x, const float* __restrict__ W,
                         const float* __restrict__ bias, float* __restrict__ t,
                         __half* __restrict__ t16)
{
    int row = blockIdx.x;
    int d   = blockIdx.y * 256 + threadIdx.x;
    int g = row >> 9, s = row & 511;
    int b = g >> 1, half = g & 1;
    const float* xp = x + (size_t)b * 20480 + (size_t)half * 10240 + (size_t)s * 20;
    float acc = bias[d];
#pragma unroll
    for (int k = 0; k < 20; k++) acc += xp[k] * W[k * 512 + d];
    t  [(size_t)row * 512 + d] = acc;
    t16[(size_t)row * 512 + d] = __float2half(acc);
}

// ---------------- fp16 wmma GEMM, cp.async double-buffered ------------------
// C(MxN) = act(A16(MxK) @ B16(KxN) + bias32). BM=BN=128, BK=32, 256 thr / 8 warps.
__global__ __launch_bounds__(256)
void k_gemm_f16(int M, int N, int K,
                const __half* __restrict__ A, const __half* __restrict__ B,
                const float* __restrict__ bias, void* __restrict__ Cout,
                int relu, int out16)
{
    __shared__ __half As[2][128][40];
    __shared__ __half Bs[2][32][136];

    int tid = threadIdx.x;
    int wid = tid >> 5, lane = tid & 31;
    int warpRow = wid >> 2;            // 0..1 -> 64-row strip
    int warpCol = wid & 3;             // 0..3 -> 32-col strip
    int row0 = blockIdx.y * 128;
    int col0 = blockIdx.x * 128;

    wmma::fragment<wmma::accumulator, 16, 16, 16, float> c[4][2];
#pragma unroll
    for (int m = 0; m < 4; m++)
#pragma unroll
        for (int n = 0; n < 2; n++) wmma::fill_fragment(c[m][n], 0.0f);

    // prefetch k0 = 0 into buf 0
#pragma unroll
    for (int t = 0; t < 2; t++) {
        int ca = tid + t * 256;                 // 0..511
        int r = ca >> 2, o = (ca & 3) * 8;
        cp_async16(&As[0][r][o], A + (size_t)(row0 + r) * K + o);
        int rb = ca >> 4, ob = (ca & 15) * 8;
        cp_async16(&Bs[0][rb][ob], B + (size_t)rb * N + col0 + ob);
    }
    cp_commit();

    int nk = K >> 5;
    for (int s = 0; s < nk; s++) {
        int buf = s & 1;
        if (s + 1 < nk) {
            int k0n = (s + 1) << 5;
#pragma unroll
            for (int t = 0; t < 2; t++) {
                int ca = tid + t * 256;
                int r = ca >> 2, o = (ca & 3) * 8;
                cp_async16(&As[buf ^ 1][r][o], A + (size_t)(row0 + r) * K + k0n + o);
                int rb = ca >> 4, ob = (ca & 15) * 8;
                cp_async16(&Bs[buf ^ 1][rb][ob], B + (size_t)(k0n + rb) * N + col0 + ob);
            }
            cp_commit();
            cp_wait1();
        } else {
            cp_wait0();
        }
        __syncthreads();

#pragma unroll
        for (int kk = 0; kk < 2; kk++) {
            wmma::fragment<wmma::matrix_a, 16, 16, 16, __half, wmma::row_major> af[4];
            wmma::fragment<wmma::matrix_b, 16, 16, 16, __half, wmma::row_major> bf[2];
#pragma unroll
            for (int m = 0; m < 4; m++)
                wmma::load_matrix_sync(af[m], &As[buf][warpRow * 64 + m * 16][kk * 16], 40);
#pragma unroll
            for (int n = 0; n < 2; n++)
                wmma::load_matrix_sync(bf[n], &Bs[buf][kk * 16][warpCol * 32 + n * 16], 136);
#pragma unroll
            for (int m = 0; m < 4; m++)
#pragma unroll
                for (int n = 0; n < 2; n++)
                    wmma::mma_sync(c[m][n], af[m], bf[n], c[m][n]);
        }
        __syncthreads();
    }

    // epilogue: reuse As as per-warp fp32 staging (20KB >= 8*16*20*4B)
    float* stage = reinterpret_cast<float*>(&As[0][0][0]) + wid * 320;
#pragma unroll
    for (int m = 0; m < 4; m++)
#pragma unroll
        for (int n = 0; n < 2; n++) {
            wmma::store_matrix_sync(stage, c[m][n], 20, wmma::mem_row_major);
            __syncwarp();
            int rowBase = row0 + warpRow * 64 + m * 16;
            int colBase = col0 + warpCol * 32 + n * 16;
#pragma unroll
            for (int p = 0; p < 2; p++) {
                int fid = lane + p * 32;
                int r = fid >> 2, c4 = (fid & 3) << 2;
                float4 b4 = *(const float4*)(bias + colBase + c4);
                float v0 = stage[r * 20 + c4 + 0] + b4.x;
                float v1 = stage[r * 20 + c4 + 1] + b4.y;
                float v2 = stage[r * 20 + c4 + 2] + b4.z;
                float v3 = stage[r * 20 + c4 + 3] + b4.w;
                if (relu) {
                    v0 = fmaxf(v0, 0.f); v1 = fmaxf(v1, 0.f);
                    v2 = fmaxf(v2, 0.f); v3 = fmaxf(v3, 0.f);
                }
                size_t off = (size_t)(rowBase + r) * N + colBase + c4;
                if (out16) {
                    __half2* dst = (__half2*)((__half*)Cout + off);
                    dst[0] = __floats2half2_rn(v0, v1);
                    dst[1] = __floats2half2_rn(v2, v3);
                } else {
                    float4 v; v.x = v0; v.y = v1; v.z = v2; v.w = v3;
                    *(float4*)((float*)Cout + off) = v;
                }
            }
            __syncwarp();
        }
}

// ---------------- scores (fp16 wmma): sc = scale*QK^T + alibi --------------
__global__ __launch_bounds__(128)
void k_scores(const __half* __restrict__ qkv, float* __restrict__ sc)
{
    __shared__ __half Qs[64][72];
    __shared__ __half Ks[64][72];
    __shared__ float stage[4][16][20];

    int bh = blockIdx.z; int g = bh >> 3, h = bh & 7;
    int i0 = blockIdx.y * 64, j0 = blockIdx.x * 64;
    int tid = threadIdx.x, wid = tid >> 5, lane = tid & 31;
    const size_t base = (size_t)g * 512 * 1536 + h * 64;

#pragma unroll
    for (int t = 0; t < 4; t++) {
        int cid = tid + t * 128;               // 0..511
        int r = cid >> 3, o = (cid & 7) * 8;
        *(float4*)&Qs[r][o] = *(const float4*)(qkv + base + (size_t)(i0 + r) * 1536 + o);
        *(float4*)&Ks[r][o] = *(const float4*)(qkv + base + 512 + (size_t)(j0 + r) * 1536 + o);
    }
    __syncthreads();

    wmma::fragment<wmma::accumulator, 16, 16, 16, float> c[4];
#pragma unroll
    for (int n = 0; n < 4; n++) wmma::fill_fragment(c[n], 0.0f);

#pragma unroll
    for (int kk = 0; kk < 4; kk++) {
        wmma::fragment<wmma::matrix_a, 16, 16, 16, __half, wmma::row_major> af;
        wmma::load_matrix_sync(af, &Qs[wid * 16][kk * 16], 72);
#pragma unroll
        for (int n = 0; n < 4; n++) {
            wmma::fragment<wmma::matrix_b, 16, 16, 16, __half, wmma::col_major> bf;
            wmma::load_matrix_sync(bf, &Ks[n * 16][kk * 16], 72);
            wmma::mma_sync(c[n], af, bf, c[n]);
        }
    }

    float slope = 1.0f / (float)(1 << (h >> 2));
    float* out = sc + ((size_t)bh * 512) * 512;
#pragma unroll
    for (int n = 0; n < 4; n++) {
        wmma::store_matrix_sync(&stage[wid][0][0], c[n], 20, wmma::mem_row_major);
        __syncwarp();
#pragma unroll
        for (int p = 0; p < 2; p++) {
            int fid = lane + p * 32;
            int r = fid >> 2, c4 = (fid & 3) << 2;
            int ig = i0 + wid * 16 + r;
            int jg = j0 + n * 16 + c4;
            float4 v;
            v.x = stage[wid][r][c4 + 0] * 0.125f - slope * fabsf((float)(ig - jg));
            v.y = stage[wid][r][c4 + 1] * 0.125f - slope * fabsf((float)(ig - jg - 1));
            v.z = stage[wid][r][c4 + 2] * 0.125f - slope * fabsf((float)(ig - jg - 2));
            v.w = stage[wid][r][c4 + 3] * 0.125f - slope * fabsf((float)(ig - jg - 3));
            *(float4*)(out + (size_t)ig * 512 + jg) = v;
        }
        __syncwarp();
    }
}

// ---------------- rowwise softmax over 512 ---------------------------------
__global__ void k_softmax(float* __restrict__ sc)
{
    size_t row = blockIdx.x;
    float4* p = (float4*)(sc + row * 512);
    int tid = threadIdx.x;                // 128
    float4 v = p[tid];
    float mx = fmaxf(fmaxf(v.x, v.y), fmaxf(v.z, v.w));
#pragma unroll
    for (int s = 16; s > 0; s >>= 1) mx = fmaxf(mx, __shfl_xor_sync(0xffffffff, mx, s));
    __shared__ float red[4];
    if ((tid & 31) == 0) red[tid >> 5] = mx;
    __syncthreads();
    mx = fmaxf(fmaxf(red[0], red[1]), fmaxf(red[2], red[3]));
    v.x = expf(v.x - mx); v.y = expf(v.y - mx);
    v.z = expf(v.z - mx); v.w = expf(v.w - mx);
    float sum = v.x + v.y + v.z + v.w;
#pragma unroll
    for (int s = 16; s > 0; s >>= 1) sum += __shfl_xor_sync(0xffffffff, sum, s);
    __shared__ float red2[4];
    if ((tid & 31) == 0) red2[tid >> 5] = sum;
    __syncthreads();
    float inv = 1.0f / (red2[0] + red2[1] + red2[2] + red2[3]);
    v.x *= inv; v.y *= inv; v.z *= inv; v.w *= inv;
    p[tid] = v;
}

// ---------------- PV (fp16 wmma): o = attn @ V ------------------------------
__global__ __launch_bounds__(128)
void k_pv(const float* __restrict__ sc, const __half* __restrict__ qkv,
          float* __restrict__ o)
{
    __shared__ __half Ps[64][40];
    __shared__ __half Vs[32][72];

    int bh = blockIdx.y; int g = bh >> 3, h = bh & 7;
    int i0 = blockIdx.x * 64;
    int tid = threadIdx.x, wid = tid >> 5;
    const float* prow = sc + ((size_t)bh * 512 + i0) * 512;
    const size_t vbase = (size_t)g * 512 * 1536 + 1024 + h * 64;

    wmma::fragment<wmma::accumulator, 16, 16, 16, float> c[4];
#pragma unroll
    for (int n = 0; n < 4; n++) wmma::fill_fragment(c[n], 0.0f);

    for (int k0 = 0; k0 < 512; k0 += 32) {
#pragma unroll
        for (int t = 0; t < 4; t++) {
            int cid = tid + t * 128;          // 0..511
            int r = cid >> 3, ofs = (cid & 7) * 4;
            float4 p4 = *(const float4*)(prow + (size_t)r * 512 + k0 + ofs);
            __half2* dst = (__half2*)&Ps[r][ofs];
            dst[0] = __floats2half2_rn(p4.x, p4.y);
            dst[1] = __floats2half2_rn(p4.z, p4.w);
        }
#pragma unroll
        for (int t = 0; t < 2; t++) {
            int cid = tid + t * 128;          // 0..255
            int r = cid >> 3, ofs = (cid & 7) * 8;
            *(float4*)&Vs[r][ofs] = *(const float4*)(qkv + vbase + (size_t)(k0 + r) * 1536 + ofs);
        }
        __syncthreads();
#pragma unroll
        for (int kk = 0; kk < 2; kk++) {
            wmma::fragment<wmma::matrix_a, 16, 16, 16, __half, wmma::row_major> af;
            wmma::load_matrix_sync(af, &Ps[wid * 16][kk * 16], 40);
#pragma unroll
            for (int n = 0; n < 4; n++) {
                wmma::fragment<wmma::matrix_b, 16, 16, 16, __half, wmma::row_major> bf;
                wmma::load_matrix_sync(bf, &Vs[kk * 16][n * 16], 72);
                wmma::mma_sync(c[n], af, bf, c[n]);
            }
        }
        __syncthreads();
    }

    float* op = o + ((size_t)g * 512 + i0 + wid * 16) * 512 + h * 64;
#pragma unroll
    for (int n = 0; n < 4; n++)
        wmma::store_matrix_sync(op + n * 16, c[n], 512, wmma::mem_row_major);
}

// ---------------- fused residual-add + LayerNorm (writes fp32 + fp16) ------
__global__ void k_addln(const float* __restrict__ res, const float* __restrict__ add,
                        const float* __restrict__ gam, const float* __restrict__ bet,
                        float* __restrict__ out, __half* __restrict__ out16)
{
    size_t row = blockIdx.x;
    int tid = threadIdx.x; // 128
    float v[4];
    float s = 0.f;
#pragma unroll
    for (int i = 0; i < 4; i++) {
        int c = tid + i * 128;
        v[i] = res[row * 512 + c] + add[row * 512 + c];
        s += v[i];
    }
    __shared__ float red[128];
    red[tid] = s; __syncthreads();
    for (int st = 64; st > 0; st >>= 1) { if (tid < st) red[tid] += red[tid + st]; __syncthreads(); }
    float mean = red[0] * (1.f / 512.f);
    __syncthreads();
    float s2 = 0.f;
#pragma unroll
    for (int i = 0; i < 4; i++) { float d = v[i] - mean; s2 += d * d; }
    red[tid] = s2; __syncthreads();
    for (int st = 64; st > 0; st >>= 1) { if (tid < st) red[tid] += red[tid + st]; __syncthreads(); }
    float inv = 1.0f / sqrtf(red[0] * (1.f / 512.f) + 1e-5f);
#pragma unroll
    for (int i = 0; i < 4; i++) {
        int c = tid + i * 128;
        float y = (v[i] - mean) * inv * gam[c] + bet[c];
        out  [row * 512 + c] = y;
        out16[row * 512 + c] = __float2half(y);
    }
}

// ---------------- out proj --------------------------------------------------
__global__ __launch_bounds__(256)
void k_outproj(const float* __restrict__ t, const float* __restrict__ W,
               const float* __restrict__ bias, float* __restrict__ hout)
{
    __shared__ float Ws[128][32];
    __shared__ float As[8][128];
    int tid = threadIdx.x;
    int r = tid >> 5, c = tid & 31;
    int row0 = blockIdx.x * 8;
    float acc = bias[c];
    for (int k0 = 0; k0 < 512; k0 += 128) {
        for (int tt = tid; tt < 4096; tt += 256)
            Ws[tt >> 5][tt & 31] = W[(size_t)(k0 + (tt >> 5)) * 32 + (tt & 31)];
        for (int tt = tid; tt < 1024; tt += 256)
            As[tt >> 7][tt & 127] = t[(size_t)(row0 + (tt >> 7)) * 512 + k0 + (tt & 127)];
        __syncthreads();
#pragma unroll 16
        for (int k = 0; k < 128; k++) acc += As[r][k] * Ws[k][c];
        __syncthreads();
    }
    int row = row0 + r;
    int g = row >> 9, s = row & 511;
    int b = g >> 1, half = g & 1;
    hout[(size_t)b * 32768 + half * 16384 + s * 32 + c] = acc;
}

// ---------------- MLP head --------------------------------------------------
__global__ __launch_bounds__(256)
void k_head(const float* __restrict__ h,
            const float* __restrict__ d1W, const float* __restrict__ d1b,
            const float* __restrict__ bn1g, const float* __restrict__ bn1b,
            const float* __restrict__ bn1m, const float* __restrict__ bn1v,
            const float* __restrict__ d2W, const float* __restrict__ d2b,
            const float* __restrict__ bn2g, const float* __restrict__ bn2b,
            const float* __restrict__ bn2m, const float* __restrict__ bn2v,
            const float* __restrict__ finW, const float* __restrict__ finb,
            float* __restrict__ out)
{
    int b = blockIdx.x;
    int tid = threadIdx.x; // 256
    __shared__ float hs[2048];
    float acc = d1b[tid];
    const float* hrow = h + (size_t)b * 32768;
    for (int k0 = 0; k0 < 32768; k0 += 2048) {
        for (int t = tid; t < 2048; t += 256) hs[t] = hrow[k0 + t];
        __syncthreads();
#pragma unroll 8
        for (int k = 0; k < 2048; k++) acc += hs[k] * d1W[(size_t)(k0 + k) * 256 + tid];
        __syncthreads();
    }
    float z = fmaxf(acc, 0.f);
    __shared__ float s1[256];
    s1[tid] = (z - bn1m[tid]) / sqrtf(bn1v[tid] + 1e-5f) * bn1g[tid] + bn1b[tid];
    __syncthreads();
    __shared__ float s2[128];
    if (tid < 128) {
        float a2 = d2b[tid];
#pragma unroll 8
        for (int k = 0; k < 256; k++) a2 += s1[k] * d2W[k * 128 + tid];
        float z2 = fmaxf(a2, 0.f);
        s2[tid] = (z2 - bn2m[tid]) / sqrtf(bn2v[tid] + 1e-5f) * bn2g[tid] + bn2b[tid];
    }
    __syncthreads();
    __shared__ float red[128];
    if (tid < 128) red[tid] = s2[tid] * finW[tid];
    __syncthreads();
    for (int st = 64; st > 0; st >>= 1) {
        if (tid < st) red[tid] += red[tid + st];
        __syncthreads();
    }
    if (tid == 0) out[b] = red[0] + finb[0];
}

// ---------------- launch ----------------------------------------------------
extern "C" void kernel_launch(void* const* d_in, const int* in_sizes, int n_in,
                              void* d_out, int out_size)
{
    const float* x      = (const float*)d_in[0];
    const float* in_W   = (const float*)d_in[1];
    const float* in_b   = (const float*)d_in[2];
    const float* qkv_W  = (const float*)d_in[3];
    const float* qkv_b  = (const float*)d_in[4];
    const float* ln1_g  = (const float*)d_in[5];
    const float* ln1_b  = (const float*)d_in[6];
    const float* ffn_W1 = (const float*)d_in[7];
    const float* ffn_b1 = (const float*)d_in[8];
    const float* ffn_W2 = (const float*)d_in[9];
    const float* ffn_b2 = (const float*)d_in[10];
    const float* ln2_g  = (const float*)d_in[11];
    const float* ln2_b  = (const float*)d_in[12];
    const float* out_W  = (const float*)d_in[13];
    const float* out_b  = (const float*)d_in[14];
    const float* d1_W   = (const float*)d_in[15];
    const float* d1_b   = (const float*)d_in[16];
    const float* bn1_g  = (const float*)d_in[17];
    const float* bn1_b  = (const float*)d_in[18];
    const float* bn1_m  = (const float*)d_in[19];
    const float* bn1_v  = (const float*)d_in[20];
    const float* d2_W   = (const float*)d_in[21];
    const float* d2_b   = (const float*)d_in[22];
    const float* bn2_g  = (const float*)d_in[23];
    const float* bn2_b  = (const float*)d_in[24];
    const float* bn2_m  = (const float*)d_in[25];
    const float* bn2_v  = (const float*)d_in[26];
    const float* fin_W  = (const float*)d_in[27];
    const float* fin_b  = (const float*)d_in[28];
    float* out = (float*)d_out;

    float *t, *sc, *o, *h;
    __half *t16, *qkv, *mid, *w1, *w2, *w3;
    cudaGetSymbolAddress((void**)&t,   g_t);
    cudaGetSymbolAddress((void**)&t16, g_t16);
    cudaGetSymbolAddress((void**)&qkv, g_qkv);
    cudaGetSymbolAddress((void**)&sc,  g_sc);
    cudaGetSymbolAddress((void**)&o,   g_o);
    cudaGetSymbolAddress((void**)&mid, g_mid);
    cudaGetSymbolAddress((void**)&h,   g_h);
    cudaGetSymbolAddress((void**)&w1,  g_w1);
    cudaGetSymbolAddress((void**)&w2,  g_w2);
    cudaGetSymbolAddress((void**)&w3,  g_w3);

    // weight conversion (tiny)
    k_cvt16<<<(4 * 512 * 1536 + 255) / 256, 256>>>(qkv_W,  w1, 4 * 512 * 1536);
    k_cvt16<<<(4 * 512 * 2048 + 255) / 256, 256>>>(ffn_W1, w2, 4 * 512 * 2048);
    k_cvt16<<<(4 * 2048 * 512 + 255) / 256, 256>>>(ffn_W2, w3, 4 * 2048 * 512);

    k_inproj<<<dim3(65536, 2), 256>>>(x, in_W, in_b, t, t16);

    for (int l = 0; l < 4; l++) {
        k_gemm_f16<<<dim3(12, 512), 256>>>(NROW, 1536, 512,
                                           t16, w1 + (size_t)l * 512 * 1536,
                                           qkv_b + l * 1536, qkv, 0, 1);
        k_scores<<<dim3(8, 8, NBH), 128>>>(qkv, sc);
        k_softmax<<<(unsigned)(NBH * 512), 128>>>(sc);
        k_pv<<<dim3(8, NBH), 128>>>(sc, qkv, o);
        k_addln<<<NROW, 128>>>(t, o, ln1_g + l * 512, ln1_b + l * 512, t, t16);
        k_gemm_f16<<<dim3(16, 512), 256>>>(NROW, 2048, 512,
                                           t16, w2 + (size_t)l * 512 * 2048,
                                           ffn_b1 + l * 2048, mid, 1, 1);
        k_gemm_f16<<<dim3(4, 512), 256>>>(NROW, 512, 2048,
                                          mid, w3 + (size_t)l * 2048 * 512,
                                          ffn_b2 + l * 512, o, 0, 0);
        k_addln<<<NROW, 128>>>(t, o, ln2_g + l * 512, ln2_b + l * 512, t, t16);
    }

    k_outproj<<<8192, 256>>>(t, out_W, out_b, h);
    k_head<<<64, 256>>>(h, d1_W, d1_b, bn1_g, bn1_b, bn1_m, bn1_v,
                        d2_W, d2_b, bn2_g, bn2_b, bn2_m, bn2_v,
                        fin_W, fin_b, out);
}

// round 4
// speedup vs baseline: 4.2626x; 1.0490x over previous
#include <cuda_runtime.h>
#include <cuda_fp16.h>
#include <mma.h>
#include <math.h>
#include <stdint.h>

using namespace nvcuda;

// ---------------- problem constants ----------------
// B=64, TOK=20, D=512, H=8, L=4, S=512, HD=64, ODIM=32
#define NROW 65536          // 128*512
#define NBH  1024           // 128*8

// ---------------- scratch (device globals) ---------------------------------
__device__ float  g_t   [NROW * 512];                 // fp32 residual stream
__device__ __half g_t16 [NROW * 512];                 // fp16 shadow of t
__device__ __half g_qkv [NROW * 1536];                // fp16 qkv
__device__ float  g_o   [NROW * 512];                 // fp32 attn/ffn out
__device__ __half g_mid [NROW * 2048];                // fp16 ffn hidden
__device__ float  g_h   [64 * 32768];
__device__ __half g_w1  [4 * 512 * 1536];             // qkv_W fp16
__device__ __half g_w2  [4 * 512 * 2048];             // ffn_W1 fp16
__device__ __half g_w3  [4 * 2048 * 512];             // ffn_W2 fp16

// ---------------- cp.async helpers -----------------------------------------
__device__ __forceinline__ void cp_async16(void* smem_dst, const void* gmem_src) {
    unsigned s = (unsigned)__cvta_generic_to_shared(smem_dst);
    asm volatile("cp.async.cg.shared.global [%0], [%1], 16;\n" :: "r"(s), "l"(gmem_src));
}
__device__ __forceinline__ void cp_commit() { asm volatile("cp.async.commit_group;\n" ::: "memory"); }
__device__ __forceinline__ void cp_wait1()  { asm volatile("cp.async.wait_group 1;\n" ::: "memory"); }
__device__ __forceinline__ void cp_wait0()  { asm volatile("cp.async.wait_group 0;\n" ::: "memory"); }

// ---------------- fp32 -> fp16 convert -------------------------------------
__global__ void k_cvt16(const float* __restrict__ src, __half* __restrict__ dst, int n)
{
    int i = blockIdx.x * 256 + threadIdx.x;
    if (i < n) dst[i] = __float2half(src[i]);
}

// ---------------- input projection: one block per row ----------------------
__global__ __launch_bounds__(256)
void k_inproj(const float* __restrict__ x, const float* __restrict__ W,
              const float* __restrict__ bias, float* __restrict__ t,
              __half* __restrict__ t16)
{
    int row = blockIdx.x;
    int tid = threadIdx.x;
    int g = row >> 9, s = row & 511;
    int b = g >> 1, half = g & 1;
    __shared__ float xs[20];
    if (tid < 20)
        xs[tid] = x[(size_t)b * 20480 + (size_t)half * 10240 + (size_t)s * 20 + tid];
    __syncthreads();
#pragma unroll
    for (int p = 0; p < 2; p++) {
        int d = tid + p * 256;
        float acc = bias[d];
#pragma unroll
        for (int k = 0; k < 20; k++) acc += xs[k] * W[k * 512 + d];
        t  [(size_t)row * 512 + d] = acc;
        t16[(size_t)row * 512 + d] = __float2half(acc);
    }
}

// ---------------- fp16 wmma GEMM, cp.async double-buffered ------------------
__global__ __launch_bounds__(256)
void k_gemm_f16(int M, int N, int K,
                const __half* __restrict__ A, const __half* __restrict__ B,
                const float* __restrict__ bias, void* __restrict__ Cout,
                int relu, int out16)
{
    __shared__ __half As[2][128][40];
    __shared__ __half Bs[2][32][136];

    int tid = threadIdx.x;
    int wid = tid >> 5, lane = tid & 31;
    int warpRow = wid >> 2;
    int warpCol = wid & 3;
    int row0 = blockIdx.y * 128;
    int col0 = blockIdx.x * 128;

    wmma::fragment<wmma::accumulator, 16, 16, 16, float> c[4][2];
#pragma unroll
    for (int m = 0; m < 4; m++)
#pragma unroll
        for (int n = 0; n < 2; n++) wmma::fill_fragment(c[m][n], 0.0f);

#pragma unroll
    for (int t = 0; t < 2; t++) {
        int ca = tid + t * 256;
        int r = ca >> 2, o = (ca & 3) * 8;
        cp_async16(&As[0][r][o], A + (size_t)(row0 + r) * K + o);
        int rb = ca >> 4, ob = (ca & 15) * 8;
        cp_async16(&Bs[0][rb][ob], B + (size_t)rb * N + col0 + ob);
    }
    cp_commit();

    int nk = K >> 5;
    for (int s = 0; s < nk; s++) {
        int buf = s & 1;
        if (s + 1 < nk) {
            int k0n = (s + 1) << 5;
#pragma unroll
            for (int t = 0; t < 2; t++) {
                int ca = tid + t * 256;
                int r = ca >> 2, o = (ca & 3) * 8;
                cp_async16(&As[buf ^ 1][r][o], A + (size_t)(row0 + r) * K + k0n + o);
                int rb = ca >> 4, ob = (ca & 15) * 8;
                cp_async16(&Bs[buf ^ 1][rb][ob], B + (size_t)(k0n + rb) * N + col0 + ob);
            }
            cp_commit();
            cp_wait1();
        } else {
            cp_wait0();
        }
        __syncthreads();

#pragma unroll
        for (int kk = 0; kk < 2; kk++) {
            wmma::fragment<wmma::matrix_a, 16, 16, 16, __half, wmma::row_major> af[4];
            wmma::fragment<wmma::matrix_b, 16, 16, 16, __half, wmma::row_major> bf[2];
#pragma unroll
            for (int m = 0; m < 4; m++)
                wmma::load_matrix_sync(af[m], &As[buf][warpRow * 64 + m * 16][kk * 16], 40);
#pragma unroll
            for (int n = 0; n < 2; n++)
                wmma::load_matrix_sync(bf[n], &Bs[buf][kk * 16][warpCol * 32 + n * 16], 136);
#pragma unroll
            for (int m = 0; m < 4; m++)
#pragma unroll
                for (int n = 0; n < 2; n++)
                    wmma::mma_sync(c[m][n], af[m], bf[n], c[m][n]);
        }
        __syncthreads();
    }

    float* stage = reinterpret_cast<float*>(&As[0][0][0]) + wid * 320;
#pragma unroll
    for (int m = 0; m < 4; m++)
#pragma unroll
        for (int n = 0; n < 2; n++) {
            wmma::store_matrix_sync(stage, c[m][n], 20, wmma::mem_row_major);
            __syncwarp();
            int rowBase = row0 + warpRow * 64 + m * 16;
            int colBase = col0 + warpCol * 32 + n * 16;
#pragma unroll
            for (int p = 0; p < 2; p++) {
                int fid = lane + p * 32;
                int r = fid >> 2, c4 = (fid & 3) << 2;
                float4 b4 = *(const float4*)(bias + colBase + c4);
                float v0 = stage[r * 20 + c4 + 0] + b4.x;
                float v1 = stage[r * 20 + c4 + 1] + b4.y;
                float v2 = stage[r * 20 + c4 + 2] + b4.z;
                float v3 = stage[r * 20 + c4 + 3] + b4.w;
                if (relu) {
                    v0 = fmaxf(v0, 0.f); v1 = fmaxf(v1, 0.f);
                    v2 = fmaxf(v2, 0.f); v3 = fmaxf(v3, 0.f);
                }
                size_t off = (size_t)(rowBase + r) * N + colBase + c4;
                if (out16) {
                    __half2* dst = (__half2*)((__half*)Cout + off);
                    dst[0] = __floats2half2_rn(v0, v1);
                    dst[1] = __floats2half2_rn(v2, v3);
                } else {
                    float4 v; v.x = v0; v.y = v1; v.z = v2; v.w = v3;
                    *(float4*)((float*)Cout + off) = v;
                }
            }
            __syncwarp();
        }
}

// ---------------- fused flash attention ------------------------------------
// grid (8 i-tiles, 1024 bh), 256 thr / 8 warps. i-tile = 64 rows, j-tile = 64.
// dynamic smem layout (bytes):
//  Qs   [64][72] half   @ 0      (9216)
//  Ks   [64][72] half   @ 9216   (9216)
//  Vs   [64][72] half   @ 18432  (9216)
//  Ps   [64][72] half   @ 27648  (9216)
//  Sst  [64][68] float  @ 36864  (17408)
//  Oacc [64][68] float  @ 54272  (17408)
//  m    [64] float      @ 71680
//  l    [64] float      @ 71936
//  alp  [64] float      @ 72192
#define FLASH_SMEM 72448

__global__ __launch_bounds__(256)
void k_flash(const __half* __restrict__ qkv, float* __restrict__ o)
{
    extern __shared__ char smem[];
    __half (*Qs)[72]  = (__half(*)[72])(smem);
    __half (*Ks)[72]  = (__half(*)[72])(smem + 9216);
    __half (*Vs)[72]  = (__half(*)[72])(smem + 18432);
    __half (*Ps)[72]  = (__half(*)[72])(smem + 27648);
    float  (*Sst)[68] = (float(*)[68])(smem + 36864);
    float  (*Oacc)[68]= (float(*)[68])(smem + 54272);
    float* mrow = (float*)(smem + 71680);
    float* lrow = (float*)(smem + 71936);
    float* arow = (float*)(smem + 72192);

    int bh = blockIdx.y; int g = bh >> 3, h = bh & 7;
    int i0 = blockIdx.x * 64;
    int tid = threadIdx.x, wid = tid >> 5, lane = tid & 31;
    int warpRow = wid >> 1;       // 0..3 -> 16 rows
    int warpCol = wid & 1;        // 0..1 -> 32 cols
    const size_t base = (size_t)g * 512 * 1536 + h * 64;
    float slope = 1.0f / (float)(1 << (h >> 2));

    // load Q tile + init state
#pragma unroll
    for (int t = 0; t < 2; t++) {
        int idx = tid + t * 256;               // 0..511
        int r = idx >> 3, c8 = (idx & 7) * 8;
        *(float4*)&Qs[r][c8] = *(const float4*)(qkv + base + (size_t)(i0 + r) * 1536 + c8);
    }
    if (tid < 64) { mrow[tid] = -1e30f; lrow[tid] = 0.f; }
#pragma unroll
    for (int t = 0; t < 4; t++) {
        int f = tid + t * 256;                 // 0..1023
        int r = f >> 4, c4 = (f & 15) * 4;
        *(float4*)&Oacc[r][c4] = make_float4(0.f, 0.f, 0.f, 0.f);
    }
    __syncthreads();

    for (int j0 = 0; j0 < 512; j0 += 64) {
        // load K, V tiles
#pragma unroll
        for (int t = 0; t < 2; t++) {
            int idx = tid + t * 256;
            int r = idx >> 3, c8 = (idx & 7) * 8;
            *(float4*)&Ks[r][c8] = *(const float4*)(qkv + base + 512  + (size_t)(j0 + r) * 1536 + c8);
            *(float4*)&Vs[r][c8] = *(const float4*)(qkv + base + 1024 + (size_t)(j0 + r) * 1536 + c8);
        }
        __syncthreads();

        // S = Q @ K^T (64x64)
        {
            wmma::fragment<wmma::accumulator, 16, 16, 16, float> cS[2];
#pragma unroll
            for (int n = 0; n < 2; n++) wmma::fill_fragment(cS[n], 0.0f);
#pragma unroll
            for (int k = 0; k < 4; k++) {
                wmma::fragment<wmma::matrix_a, 16, 16, 16, __half, wmma::row_major> af;
                wmma::load_matrix_sync(af, &Qs[warpRow * 16][k * 16], 72);
#pragma unroll
                for (int n = 0; n < 2; n++) {
                    wmma::fragment<wmma::matrix_b, 16, 16, 16, __half, wmma::col_major> bf;
                    wmma::load_matrix_sync(bf, &Ks[warpCol * 32 + n * 16][k * 16], 72);
                    wmma::mma_sync(cS[n], af, bf, cS[n]);
                }
            }
#pragma unroll
            for (int n = 0; n < 2; n++)
                wmma::store_matrix_sync(&Sst[warpRow * 16][warpCol * 32 + n * 16], cS[n],
                                        68, wmma::mem_row_major);
        }
        __syncthreads();

        // online softmax update, warp w owns rows [w*8, w*8+8)
#pragma unroll
        for (int rr = 0; rr < 8; rr++) {
            int r = wid * 8 + rr;
            int ig = i0 + r;
            int jg = j0 + 2 * lane;
            float s0 = Sst[r][2 * lane]     * 0.125f - slope * fabsf((float)(ig - jg));
            float s1 = Sst[r][2 * lane + 1] * 0.125f - slope * fabsf((float)(ig - jg - 1));
            float mx = fmaxf(s0, s1);
#pragma unroll
            for (int sft = 16; sft > 0; sft >>= 1)
                mx = fmaxf(mx, __shfl_xor_sync(0xffffffff, mx, sft));
            float mold = mrow[r];
            float mnew = fmaxf(mold, mx);
            float p0 = __expf(s0 - mnew);
            float p1 = __expf(s1 - mnew);
            float rs = p0 + p1;
#pragma unroll
            for (int sft = 16; sft > 0; sft >>= 1)
                rs += __shfl_xor_sync(0xffffffff, rs, sft);
            if (lane == 0) {
                float al = __expf(mold - mnew);
                lrow[r] = lrow[r] * al + rs;
                mrow[r] = mnew;
                arow[r] = al;
            }
            *(__half2*)&Ps[r][2 * lane] = __floats2half2_rn(p0, p1);
        }
        __syncthreads();

        // PV = P @ V (64x64) -> stage
        {
            wmma::fragment<wmma::accumulator, 16, 16, 16, float> cO[2];
#pragma unroll
            for (int n = 0; n < 2; n++) wmma::fill_fragment(cO[n], 0.0f);
#pragma unroll
            for (int k = 0; k < 4; k++) {
                wmma::fragment<wmma::matrix_a, 16, 16, 16, __half, wmma::row_major> af;
                wmma::load_matrix_sync(af, &Ps[warpRow * 16][k * 16], 72);
#pragma unroll
                for (int n = 0; n < 2; n++) {
                    wmma::fragment<wmma::matrix_b, 16, 16, 16, __half, wmma::row_major> bf;
                    wmma::load_matrix_sync(bf, &Vs[k * 16][warpCol * 32 + n * 16], 72);
                    wmma::mma_sync(cO[n], af, bf, cO[n]);
                }
            }
#pragma unroll
            for (int n = 0; n < 2; n++)
                wmma::store_matrix_sync(&Sst[warpRow * 16][warpCol * 32 + n * 16], cO[n],
                                        68, wmma::mem_row_major);
        }
        __syncthreads();

        // O = O * alpha[r] + PV
#pragma unroll
        for (int t = 0; t < 4; t++) {
            int f = tid + t * 256;
            int r = f >> 4, c4 = (f & 15) * 4;
            float al = arow[r];
            float4 ov = *(float4*)&Oacc[r][c4];
            float4 pv = *(float4*)&Sst[r][c4];
            ov.x = ov.x * al + pv.x;
            ov.y = ov.y * al + pv.y;
            ov.z = ov.z * al + pv.z;
            ov.w = ov.w * al + pv.w;
            *(float4*)&Oacc[r][c4] = ov;
        }
        __syncthreads();
    }

    // normalize + write out
#pragma unroll
    for (int t = 0; t < 4; t++) {
        int f = tid + t * 256;
        int r = f >> 4, c4 = (f & 15) * 4;
        float inv = 1.0f / lrow[r];
        float4 ov = *(float4*)&Oacc[r][c4];
        ov.x *= inv; ov.y *= inv; ov.z *= inv; ov.w *= inv;
        *(float4*)(o + ((size_t)g * 512 + i0 + r) * 512 + h * 64 + c4) = ov;
    }
}

// ---------------- fused residual-add + LayerNorm (writes fp32 + fp16) ------
__global__ void k_addln(const float* __restrict__ res, const float* __restrict__ add,
                        const float* __restrict__ gam, const float* __restrict__ bet,
                        float* __restrict__ out, __half* __restrict__ out16)
{
    size_t row = blockIdx.x;
    int tid = threadIdx.x; // 128
    float v[4];
    float s = 0.f;
#pragma unroll
    for (int i = 0; i < 4; i++) {
        int c = tid + i * 128;
        v[i] = res[row * 512 + c] + add[row * 512 + c];
        s += v[i];
    }
    __shared__ float red[128];
    red[tid] = s; __syncthreads();
    for (int st = 64; st > 0; st >>= 1) { if (tid < st) red[tid] += red[tid + st]; __syncthreads(); }
    float mean = red[0] * (1.f / 512.f);
    __syncthreads();
    float s2 = 0.f;
#pragma unroll
    for (int i = 0; i < 4; i++) { float d = v[i] - mean; s2 += d * d; }
    red[tid] = s2; __syncthreads();
    for (int st = 64; st > 0; st >>= 1) { if (tid < st) red[tid] += red[tid + st]; __syncthreads(); }
    float inv = 1.0f / sqrtf(red[0] * (1.f / 512.f) + 1e-5f);
#pragma unroll
    for (int i = 0; i < 4; i++) {
        int c = tid + i * 128;
        float y = (v[i] - mean) * inv * gam[c] + bet[c];
        out  [row * 512 + c] = y;
        out16[row * 512 + c] = __float2half(y);
    }
}

// ---------------- out proj --------------------------------------------------
__global__ __launch_bounds__(256)
void k_outproj(const float* __restrict__ t, const float* __restrict__ W,
               const float* __restrict__ bias, float* __restrict__ hout)
{
    __shared__ float Ws[128][32];
    __shared__ float As[8][128];
    int tid = threadIdx.x;
    int r = tid >> 5, c = tid & 31;
    int row0 = blockIdx.x * 8;
    float acc = bias[c];
    for (int k0 = 0; k0 < 512; k0 += 128) {
        for (int tt = tid; tt < 4096; tt += 256)
            Ws[tt >> 5][tt & 31] = W[(size_t)(k0 + (tt >> 5)) * 32 + (tt & 31)];
        for (int tt = tid; tt < 1024; tt += 256)
            As[tt >> 7][tt & 127] = t[(size_t)(row0 + (tt >> 7)) * 512 + k0 + (tt & 127)];
        __syncthreads();
#pragma unroll 16
        for (int k = 0; k < 128; k++) acc += As[r][k] * Ws[k][c];
        __syncthreads();
    }
    int row = row0 + r;
    int g = row >> 9, s = row & 511;
    int b = g >> 1, half = g & 1;
    hout[(size_t)b * 32768 + half * 16384 + s * 32 + c] = acc;
}

// ---------------- MLP head --------------------------------------------------
__global__ __launch_bounds__(256)
void k_head(const float* __restrict__ h,
            const float* __restrict__ d1W, const float* __restrict__ d1b,
            const float* __restrict__ bn1g, const float* __restrict__ bn1b,
            const float* __restrict__ bn1m, const float* __restrict__ bn1v,
            const float* __restrict__ d2W, const float* __restrict__ d2b,
            const float* __restrict__ bn2g, const float* __restrict__ bn2b,
            const float* __restrict__ bn2m, const float* __restrict__ bn2v,
            const float* __restrict__ finW, const float* __restrict__ finb,
            float* __restrict__ out)
{
    int b = blockIdx.x;
    int tid = threadIdx.x; // 256
    __shared__ float hs[2048];
    float acc = d1b[tid];
    const float* hrow = h + (size_t)b * 32768;
    for (int k0 = 0; k0 < 32768; k0 += 2048) {
        for (int t = tid; t < 2048; t += 256) hs[t] = hrow[k0 + t];
        __syncthreads();
#pragma unroll 8
        for (int k = 0; k < 2048; k++) acc += hs[k] * d1W[(size_t)(k0 + k) * 256 + tid];
        __syncthreads();
    }
    float z = fmaxf(acc, 0.f);
    __shared__ float s1[256];
    s1[tid] = (z - bn1m[tid]) / sqrtf(bn1v[tid] + 1e-5f) * bn1g[tid] + bn1b[tid];
    __syncthreads();
    __shared__ float s2[128];
    if (tid < 128) {
        float a2 = d2b[tid];
#pragma unroll 8
        for (int k = 0; k < 256; k++) a2 += s1[k] * d2W[k * 128 + tid];
        float z2 = fmaxf(a2, 0.f);
        s2[tid] = (z2 - bn2m[tid]) / sqrtf(bn2v[tid] + 1e-5f) * bn2g[tid] + bn2b[tid];
    }
    __syncthreads();
    __shared__ float red[128];
    if (tid < 128) red[tid] = s2[tid] * finW[tid];
    __syncthreads();
    for (int st = 64; st > 0; st >>= 1) {
        if (tid < st) red[tid] += red[tid + st];
        __syncthreads();
    }
    if (tid == 0) out[b] = red[0] + finb[0];
}

// ---------------- launch ----------------------------------------------------
extern "C" void kernel_launch(void* const* d_in, const int* in_sizes, int n_in,
                              void* d_out, int out_size)
{
    const float* x      = (const float*)d_in[0];
    const float* in_W   = (const float*)d_in[1];
    const float* in_b   = (const float*)d_in[2];
    const float* qkv_W  = (const float*)d_in[3];
    const float* qkv_b  = (const float*)d_in[4];
    const float* ln1_g  = (const float*)d_in[5];
    const float* ln1_b  = (const float*)d_in[6];
    const float* ffn_W1 = (const float*)d_in[7];
    const float* ffn_b1 = (const float*)d_in[8];
    const float* ffn_W2 = (const float*)d_in[9];
    const float* ffn_b2 = (const float*)d_in[10];
    const float* ln2_g  = (const float*)d_in[11];
    const float* ln2_b  = (const float*)d_in[12];
    const float* out_W  = (const float*)d_in[13];
    const float* out_b  = (const float*)d_in[14];
    const float* d1_W   = (const float*)d_in[15];
    const float* d1_b   = (const float*)d_in[16];
    const float* bn1_g  = (const float*)d_in[17];
    const float* bn1_b  = (const float*)d_in[18];
    const float* bn1_m  = (const float*)d_in[19];
    const float* bn1_v  = (const float*)d_in[20];
    const float* d2_W   = (const float*)d_in[21];
    const float* d2_b   = (const float*)d_in[22];
    const float* bn2_g  = (const float*)d_in[23];
    const float* bn2_b  = (const float*)d_in[24];
    const float* bn2_m  = (const float*)d_in[25];
    const float* bn2_v  = (const float*)d_in[26];
    const float* fin_W  = (const float*)d_in[27];
    const float* fin_b  = (const float*)d_in[28];
    float* out = (float*)d_out;

    float *t, *o, *h;
    __half *t16, *qkv, *mid, *w1, *w2, *w3;
    cudaGetSymbolAddress((void**)&t,   g_t);
    cudaGetSymbolAddress((void**)&t16, g_t16);
    cudaGetSymbolAddress((void**)&qkv, g_qkv);
    cudaGetSymbolAddress((void**)&o,   g_o);
    cudaGetSymbolAddress((void**)&mid, g_mid);
    cudaGetSymbolAddress((void**)&h,   g_h);
    cudaGetSymbolAddress((void**)&w1,  g_w1);
    cudaGetSymbolAddress((void**)&w2,  g_w2);
    cudaGetSymbolAddress((void**)&w3,  g_w3);

    static int smem_set = 0;
    if (!smem_set) {
        cudaFuncSetAttribute(k_flash, cudaFuncAttributeMaxDynamicSharedMemorySize, FLASH_SMEM);
        smem_set = 1;
    }

    k_cvt16<<<(4 * 512 * 1536 + 255) / 256, 256>>>(qkv_W,  w1, 4 * 512 * 1536);
    k_cvt16<<<(4 * 512 * 2048 + 255) / 256, 256>>>(ffn_W1, w2, 4 * 512 * 2048);
    k_cvt16<<<(4 * 2048 * 512 + 255) / 256, 256>>>(ffn_W2, w3, 4 * 2048 * 512);

    k_inproj<<<65536, 256>>>(x, in_W, in_b, t, t16);

    for (int l = 0; l < 4; l++) {
        k_gemm_f16<<<dim3(12, 512), 256>>>(NROW, 1536, 512,
                                           t16, w1 + (size_t)l * 512 * 1536,
                                           qkv_b + l * 1536, qkv, 0, 1);
        k_flash<<<dim3(8, NBH), 256, FLASH_SMEM>>>(qkv, o);
        k_addln<<<NROW, 128>>>(t, o, ln1_g + l * 512, ln1_b + l * 512, t, t16);
        k_gemm_f16<<<dim3(16, 512), 256>>>(NROW, 2048, 512,
                                           t16, w2 + (size_t)l * 512 * 2048,
                                           ffn_b1 + l * 2048, mid, 1, 1);
        k_gemm_f16<<<dim3(4, 512), 256>>>(NROW, 512, 2048,
                                          mid, w3 + (size_t)l * 2048 * 512,
                                          ffn_b2 + l * 512, o, 0, 0);
        k_addln<<<NROW, 128>>>(t, o, ln2_g + l * 512, ln2_b + l * 512, t, t16);
    }

    k_outproj<<<8192, 256>>>(t, out_W, out_b, h);
    k_head<<<64, 256>>>(h, d1_W, d1_b, bn1_g, bn1_b, bn1_m, bn1_v,
                        d2_W, d2_b, bn2_g, bn2_b, bn2_m, bn2_v,
                        fin_W, fin_b, out);
}

// round 5
// speedup vs baseline: 4.7257x; 1.1086x over previous
#include <cuda_runtime.h>
#include <cuda_fp16.h>
#include <mma.h>
#include <math.h>
#include <stdint.h>

using namespace nvcuda;

// ---------------- problem constants ----------------
#define NROW 65536          // 128*512
#define NBH  1024           // 128*8

// ---------------- scratch (device globals) ---------------------------------
__device__ float  g_t   [NROW * 512];
__device__ __half g_t16 [NROW * 512];
__device__ __half g_qkv [NROW * 1536];
__device__ float  g_o   [NROW * 512];
__device__ __half g_mid [NROW * 2048];
__device__ float  g_h   [64 * 32768];
__device__ __half g_w1  [4 * 512 * 1536];
__device__ __half g_w2  [4 * 512 * 2048];
__device__ __half g_w3  [4 * 2048 * 512];

// ---------------- cp.async helpers -----------------------------------------
__device__ __forceinline__ void cp_async16(void* smem_dst, const void* gmem_src) {
    unsigned s = (unsigned)__cvta_generic_to_shared(smem_dst);
    asm volatile("cp.async.cg.shared.global [%0], [%1], 16;\n" :: "r"(s), "l"(gmem_src));
}
__device__ __forceinline__ void cp_commit() { asm volatile("cp.async.commit_group;\n" ::: "memory"); }
__device__ __forceinline__ void cp_wait1()  { asm volatile("cp.async.wait_group 1;\n" ::: "memory"); }

// ---------------- fp32 -> fp16 convert -------------------------------------
__global__ void k_cvt16(const float* __restrict__ src, __half* __restrict__ dst, int n)
{
    int i = blockIdx.x * 256 + threadIdx.x;
    if (i < n) dst[i] = __float2half(src[i]);
}

// ---------------- input projection ------------------------------------------
__global__ __launch_bounds__(256)
void k_inproj(const float* __restrict__ x, const float* __restrict__ W,
              const float* __restrict__ bias, float* __restrict__ t,
              __half* __restrict__ t16)
{
    int row = blockIdx.x;
    int tid = threadIdx.x;
    int g = row >> 9, s = row & 511;
    int b = g >> 1, half = g & 1;
    __shared__ float xs[20];
    if (tid < 20)
        xs[tid] = x[(size_t)b * 20480 + (size_t)half * 10240 + (size_t)s * 20 + tid];
    __syncthreads();
#pragma unroll
    for (int p = 0; p < 2; p++) {
        int d = tid + p * 256;
        float acc = bias[d];
#pragma unroll
        for (int k = 0; k < 20; k++) acc += xs[k] * W[k * 512 + d];
        t  [(size_t)row * 512 + d] = acc;
        t16[(size_t)row * 512 + d] = __float2half(acc);
    }
}

// ---------------- fp16 wmma GEMM: 3-stage cp.async, BK=64 -------------------
// BM=BN=128, BK=64, 256 thr / 8 warps (2x4), warp tile 64x32.
// dynamic smem: As 3*128*72 halves, Bs 3*64*136 halves = 107520 B
#define GEMM_SMEM (3 * 128 * 72 * 2 + 3 * 64 * 136 * 2)

__global__ __launch_bounds__(256, 2)
void k_gemm_f16(int M, int N, int K,
                const __half* __restrict__ A, const __half* __restrict__ B,
                const float* __restrict__ bias, void* __restrict__ Cout,
                int relu, int out16)
{
    extern __shared__ __half sm[];
    __half* AsBase = sm;                       // stage s: + s*128*72
    __half* BsBase = sm + 3 * 128 * 72;        // stage s: + s*64*136

    int tid = threadIdx.x;
    int wid = tid >> 5, lane = tid & 31;
    int warpRow = wid >> 2;            // 0..1 -> 64-row strip
    int warpCol = wid & 3;             // 0..3 -> 32-col strip
    int row0 = blockIdx.y * 128;
    int col0 = blockIdx.x * 128;

    wmma::fragment<wmma::accumulator, 16, 16, 16, float> c[4][2];
#pragma unroll
    for (int m = 0; m < 4; m++)
#pragma unroll
        for (int n = 0; n < 2; n++) wmma::fill_fragment(c[m][n], 0.0f);

    auto issue_stage = [&](int st, int k0) {
        __half* As = AsBase + st * 128 * 72;
        __half* Bs = BsBase + st * 64 * 136;
#pragma unroll
        for (int t = 0; t < 4; t++) {
            int ca = tid + t * 256;                  // 0..1023
            int r  = ca >> 3, c8 = (ca & 7) * 8;     // A: 128 x 64
            cp_async16(As + r * 72 + c8, A + (size_t)(row0 + r) * K + k0 + c8);
            int rb = ca >> 4, cb = (ca & 15) * 8;    // B: 64 x 128
            cp_async16(Bs + rb * 136 + cb, B + (size_t)(k0 + rb) * N + col0 + cb);
        }
    };

    int nk = K >> 6;                   // K=512 -> 8, K=2048 -> 32 (always >=2)
    issue_stage(0, 0);   cp_commit();
    issue_stage(1, 64);  cp_commit();

    for (int s = 0; s < nk; s++) {
        cp_wait1();                    // group s complete (FIFO, <=1 pending)
        __syncthreads();               // all copies visible; prev reads of reused buf done
        if (s + 2 < nk) issue_stage((s + 2) % 3, (s + 2) << 6);
        cp_commit();                   // always commit (keeps wait_group accounting exact)

        __half* As = AsBase + (s % 3) * 128 * 72;
        __half* Bs = BsBase + (s % 3) * 64 * 136;
#pragma unroll
        for (int kk = 0; kk < 4; kk++) {
            wmma::fragment<wmma::matrix_b, 16, 16, 16, __half, wmma::row_major> bf[2];
#pragma unroll
            for (int n = 0; n < 2; n++)
                wmma::load_matrix_sync(bf[n], Bs + (kk * 16) * 136 + warpCol * 32 + n * 16, 136);
#pragma unroll
            for (int m = 0; m < 4; m++) {
                wmma::fragment<wmma::matrix_a, 16, 16, 16, __half, wmma::row_major> af;
                wmma::load_matrix_sync(af, As + (warpRow * 64 + m * 16) * 72 + kk * 16, 72);
                wmma::mma_sync(c[m][0], af, bf[0], c[m][0]);
                wmma::mma_sync(c[m][1], af, bf[1], c[m][1]);
            }
        }
    }
    __syncthreads();   // protect smem reuse by epilogue staging

    float* stage = reinterpret_cast<float*>(sm) + wid * 320;
#pragma unroll
    for (int m = 0; m < 4; m++)
#pragma unroll
        for (int n = 0; n < 2; n++) {
            wmma::store_matrix_sync(stage, c[m][n], 20, wmma::mem_row_major);
            __syncwarp();
            int rowBase = row0 + warpRow * 64 + m * 16;
            int colBase = col0 + warpCol * 32 + n * 16;
#pragma unroll
            for (int p = 0; p < 2; p++) {
                int fid = lane + p * 32;
                int r = fid >> 2, c4 = (fid & 3) << 2;
                float4 b4 = *(const float4*)(bias + colBase + c4);
                float v0 = stage[r * 20 + c4 + 0] + b4.x;
                float v1 = stage[r * 20 + c4 + 1] + b4.y;
                float v2 = stage[r * 20 + c4 + 2] + b4.z;
                float v3 = stage[r * 20 + c4 + 3] + b4.w;
                if (relu) {
                    v0 = fmaxf(v0, 0.f); v1 = fmaxf(v1, 0.f);
                    v2 = fmaxf(v2, 0.f); v3 = fmaxf(v3, 0.f);
                }
                size_t off = (size_t)(rowBase + r) * N + colBase + c4;
                if (out16) {
                    __half2* dst = (__half2*)((__half*)Cout + off);
                    dst[0] = __floats2half2_rn(v0, v1);
                    dst[1] = __floats2half2_rn(v2, v3);
                } else {
                    float4 v; v.x = v0; v.y = v1; v.z = v2; v.w = v3;
                    *(float4*)((float*)Cout + off) = v;
                }
            }
            __syncwarp();
        }
}

// ---------------- fused flash attention ------------------------------------
// grid (8 i-tiles, 1024 bh), 256 thr / 8 warps.
#define FLASH_SMEM 72448

__global__ __launch_bounds__(256)
void k_flash(const __half* __restrict__ qkv, float* __restrict__ o)
{
    extern __shared__ char smem[];
    __half (*Qs)[72]  = (__half(*)[72])(smem);
    __half (*Ks)[72]  = (__half(*)[72])(smem + 9216);
    __half (*Vs)[72]  = (__half(*)[72])(smem + 18432);
    __half (*Ps)[72]  = (__half(*)[72])(smem + 27648);
    float  (*Sst)[68] = (float(*)[68])(smem + 36864);
    float  (*Oacc)[68]= (float(*)[68])(smem + 54272);
    float* mrow = (float*)(smem + 71680);
    float* lrow = (float*)(smem + 71936);
    float* arow = (float*)(smem + 72192);

    int bh = blockIdx.y; int g = bh >> 3, h = bh & 7;
    int i0 = blockIdx.x * 64;
    int tid = threadIdx.x, wid = tid >> 5;
    int warpRow = wid >> 1;       // 0..3 -> 16 rows
    int warpCol = wid & 1;        // 0..1 -> 32 cols
    const size_t base = (size_t)g * 512 * 1536 + h * 64;
    float slope = 1.0f / (float)(1 << (h >> 2));

#pragma unroll
    for (int t = 0; t < 2; t++) {
        int idx = tid + t * 256;
        int r = idx >> 3, c8 = (idx & 7) * 8;
        *(float4*)&Qs[r][c8] = *(const float4*)(qkv + base + (size_t)(i0 + r) * 1536 + c8);
    }
    if (tid < 64) { mrow[tid] = -1e30f; lrow[tid] = 0.f; }
#pragma unroll
    for (int t = 0; t < 4; t++) {
        int f = tid + t * 256;
        int r = f >> 4, c4 = (f & 15) * 4;
        *(float4*)&Oacc[r][c4] = make_float4(0.f, 0.f, 0.f, 0.f);
    }
    __syncthreads();

    for (int j0 = 0; j0 < 512; j0 += 64) {
#pragma unroll
        for (int t = 0; t < 2; t++) {
            int idx = tid + t * 256;
            int r = idx >> 3, c8 = (idx & 7) * 8;
            *(float4*)&Ks[r][c8] = *(const float4*)(qkv + base + 512  + (size_t)(j0 + r) * 1536 + c8);
            *(float4*)&Vs[r][c8] = *(const float4*)(qkv + base + 1024 + (size_t)(j0 + r) * 1536 + c8);
        }
        __syncthreads();

        // S = Q @ K^T
        {
            wmma::fragment<wmma::accumulator, 16, 16, 16, float> cS[2];
#pragma unroll
            for (int n = 0; n < 2; n++) wmma::fill_fragment(cS[n], 0.0f);
#pragma unroll
            for (int k = 0; k < 4; k++) {
                wmma::fragment<wmma::matrix_a, 16, 16, 16, __half, wmma::row_major> af;
                wmma::load_matrix_sync(af, &Qs[warpRow * 16][k * 16], 72);
#pragma unroll
                for (int n = 0; n < 2; n++) {
                    wmma::fragment<wmma::matrix_b, 16, 16, 16, __half, wmma::col_major> bf;
                    wmma::load_matrix_sync(bf, &Ks[warpCol * 32 + n * 16][k * 16], 72);
                    wmma::mma_sync(cS[n], af, bf, cS[n]);
                }
            }
#pragma unroll
            for (int n = 0; n < 2; n++)
                wmma::store_matrix_sync(&Sst[warpRow * 16][warpCol * 32 + n * 16], cS[n],
                                        68, wmma::mem_row_major);
        }
        __syncthreads();

        // online softmax: one quad (4 threads) per row, 16 cols each
        {
            int r = tid >> 2;              // 0..63
            int e = tid & 3;
            int ig = i0 + r;
            float4 s4[4];
            float mx = -1e30f;
#pragma unroll
            for (int i = 0; i < 4; i++) {
                float4 v = *(float4*)&Sst[r][e * 16 + i * 4];
                int jb = j0 + e * 16 + i * 4;
                v.x = v.x * 0.125f - slope * fabsf((float)(ig - jb));
                v.y = v.y * 0.125f - slope * fabsf((float)(ig - jb - 1));
                v.z = v.z * 0.125f - slope * fabsf((float)(ig - jb - 2));
                v.w = v.w * 0.125f - slope * fabsf((float)(ig - jb - 3));
                s4[i] = v;
                mx = fmaxf(mx, fmaxf(fmaxf(v.x, v.y), fmaxf(v.z, v.w)));
            }
            mx = fmaxf(mx, __shfl_xor_sync(0xffffffff, mx, 1));
            mx = fmaxf(mx, __shfl_xor_sync(0xffffffff, mx, 2));
            float mold = mrow[r];
            float mnew = fmaxf(mold, mx);
            float sum = 0.f;
#pragma unroll
            for (int i = 0; i < 4; i++) {
                float p0 = __expf(s4[i].x - mnew);
                float p1 = __expf(s4[i].y - mnew);
                float p2 = __expf(s4[i].z - mnew);
                float p3 = __expf(s4[i].w - mnew);
                sum += (p0 + p1) + (p2 + p3);
                __half2* dst = (__half2*)&Ps[r][e * 16 + i * 4];
                dst[0] = __floats2half2_rn(p0, p1);
                dst[1] = __floats2half2_rn(p2, p3);
            }
            sum += __shfl_xor_sync(0xffffffff, sum, 1);
            sum += __shfl_xor_sync(0xffffffff, sum, 2);
            if (e == 0) {
                float al = __expf(mold - mnew);
                lrow[r] = lrow[r] * al + sum;
                mrow[r] = mnew;
                arow[r] = al;
            }
        }
        __syncthreads();

        // PV = P @ V
        {
            wmma::fragment<wmma::accumulator, 16, 16, 16, float> cO[2];
#pragma unroll
            for (int n = 0; n < 2; n++) wmma::fill_fragment(cO[n], 0.0f);
#pragma unroll
            for (int k = 0; k < 4; k++) {
                wmma::fragment<wmma::matrix_a, 16, 16, 16, __half, wmma::row_major> af;
                wmma::load_matrix_sync(af, &Ps[warpRow * 16][k * 16], 72);
#pragma unroll
                for (int n = 0; n < 2; n++) {
                    wmma::fragment<wmma::matrix_b, 16, 16, 16, __half, wmma::row_major> bf;
                    wmma::load_matrix_sync(bf, &Vs[k * 16][warpCol * 32 + n * 16], 72);
                    wmma::mma_sync(cO[n], af, bf, cO[n]);
                }
            }
#pragma unroll
            for (int n = 0; n < 2; n++)
                wmma::store_matrix_sync(&Sst[warpRow * 16][warpCol * 32 + n * 16], cO[n],
                                        68, wmma::mem_row_major);
        }
        __syncthreads();

        // O = O * alpha + PV
#pragma unroll
        for (int t = 0; t < 4; t++) {
            int f = tid + t * 256;
            int r = f >> 4, c4 = (f & 15) * 4;
            float al = arow[r];
            float4 ov = *(float4*)&Oacc[r][c4];
            float4 pv = *(float4*)&Sst[r][c4];
            ov.x = ov.x * al + pv.x;
            ov.y = ov.y * al + pv.y;
            ov.z = ov.z * al + pv.z;
            ov.w = ov.w * al + pv.w;
            *(float4*)&Oacc[r][c4] = ov;
        }
        __syncthreads();
    }

#pragma unroll
    for (int t = 0; t < 4; t++) {
        int f = tid + t * 256;
        int r = f >> 4, c4 = (f & 15) * 4;
        float inv = 1.0f / lrow[r];
        float4 ov = *(float4*)&Oacc[r][c4];
        ov.x *= inv; ov.y *= inv; ov.z *= inv; ov.w *= inv;
        *(float4*)(o + ((size_t)g * 512 + i0 + r) * 512 + h * 64 + c4) = ov;
    }
}

// ---------------- fused residual-add + LayerNorm ----------------------------
__global__ void k_addln(const float* __restrict__ res, const float* __restrict__ add,
                        const float* __restrict__ gam, const float* __restrict__ bet,
                        float* __restrict__ out, __half* __restrict__ out16)
{
    size_t row = blockIdx.x;
    int tid = threadIdx.x; // 128
    float v[4];
    float s = 0.f;
#pragma unroll
    for (int i = 0; i < 4; i++) {
        int c = tid + i * 128;
        v[i] = res[row * 512 + c] + add[row * 512 + c];
        s += v[i];
    }
    __shared__ float red[128];
    red[tid] = s; __syncthreads();
    for (int st = 64; st > 0; st >>= 1) { if (tid < st) red[tid] += red[tid + st]; __syncthreads(); }
    float mean = red[0] * (1.f / 512.f);
    __syncthreads();
    float s2 = 0.f;
#pragma unroll
    for (int i = 0; i < 4; i++) { float d = v[i] - mean; s2 += d * d; }
    red[tid] = s2; __syncthreads();
    for (int st = 64; st > 0; st >>= 1) { if (tid < st) red[tid] += red[tid + st]; __syncthreads(); }
    float inv = 1.0f / sqrtf(red[0] * (1.f / 512.f) + 1e-5f);
#pragma unroll
    for (int i = 0; i < 4; i++) {
        int c = tid + i * 128;
        float y = (v[i] - mean) * inv * gam[c] + bet[c];
        out  [row * 512 + c] = y;
        out16[row * 512 + c] = __float2half(y);
    }
}

// ---------------- out proj ---------------------------------------------------
__global__ __launch_bounds__(256)
void k_outproj(const float* __restrict__ t, const float* __restrict__ W,
               const float* __restrict__ bias, float* __restrict__ hout)
{
    __shared__ float Ws[128][32];
    __shared__ float As[8][128];
    int tid = threadIdx.x;
    int r = tid >> 5, c = tid & 31;
    int row0 = blockIdx.x * 8;
    float acc = bias[c];
    for (int k0 = 0; k0 < 512; k0 += 128) {
        for (int tt = tid; tt < 4096; tt += 256)
            Ws[tt >> 5][tt & 31] = W[(size_t)(k0 + (tt >> 5)) * 32 + (tt & 31)];
        for (int tt = tid; tt < 1024; tt += 256)
            As[tt >> 7][tt & 127] = t[(size_t)(row0 + (tt >> 7)) * 512 + k0 + (tt & 127)];
        __syncthreads();
#pragma unroll 16
        for (int k = 0; k < 128; k++) acc += As[r][k] * Ws[k][c];
        __syncthreads();
    }
    int row = row0 + r;
    int g = row >> 9, s = row & 511;
    int b = g >> 1, half = g & 1;
    hout[(size_t)b * 32768 + half * 16384 + s * 32 + c] = acc;
}

// ---------------- MLP head ----------------------------------------------------
__global__ __launch_bounds__(256)
void k_head(const float* __restrict__ h,
            const float* __restrict__ d1W, const float* __restrict__ d1b,
            const float* __restrict__ bn1g, const float* __restrict__ bn1b,
            const float* __restrict__ bn1m, const float* __restrict__ bn1v,
            const float* __restrict__ d2W, const float* __restrict__ d2b,
            const float* __restrict__ bn2g, const float* __restrict__ bn2b,
            const float* __restrict__ bn2m, const float* __restrict__ bn2v,
            const float* __restrict__ finW, const float* __restrict__ finb,
            float* __restrict__ out)
{
    int b = blockIdx.x;
    int tid = threadIdx.x; // 256
    __shared__ float hs[2048];
    float acc = d1b[tid];
    const float* hrow = h + (size_t)b * 32768;
    for (int k0 = 0; k0 < 32768; k0 += 2048) {
        for (int t = tid; t < 2048; t += 256) hs[t] = hrow[k0 + t];
        __syncthreads();
#pragma unroll 8
        for (int k = 0; k < 2048; k++) acc += hs[k] * d1W[(size_t)(k0 + k) * 256 + tid];
        __syncthreads();
    }
    float z = fmaxf(acc, 0.f);
    __shared__ float s1[256];
    s1[tid] = (z - bn1m[tid]) / sqrtf(bn1v[tid] + 1e-5f) * bn1g[tid] + bn1b[tid];
    __syncthreads();
    __shared__ float s2[128];
    if (tid < 128) {
        float a2 = d2b[tid];
#pragma unroll 8
        for (int k = 0; k < 256; k++) a2 += s1[k] * d2W[k * 128 + tid];
        float z2 = fmaxf(a2, 0.f);
        s2[tid] = (z2 - bn2m[tid]) / sqrtf(bn2v[tid] + 1e-5f) * bn2g[tid] + bn2b[tid];
    }
    __syncthreads();
    __shared__ float red[128];
    if (tid < 128) red[tid] = s2[tid] * finW[tid];
    __syncthreads();
    for (int st = 64; st > 0; st >>= 1) {
        if (tid < st) red[tid] += red[tid + st];
        __syncthreads();
    }
    if (tid == 0) out[b] = red[0] + finb[0];
}

// ---------------- launch -------------------------------------------------------
extern "C" void kernel_launch(void* const* d_in, const int* in_sizes, int n_in,
                              void* d_out, int out_size)
{
    const float* x      = (const float*)d_in[0];
    const float* in_W   = (const float*)d_in[1];
    const float* in_b   = (const float*)d_in[2];
    const float* qkv_W  = (const float*)d_in[3];
    const float* qkv_b  = (const float*)d_in[4];
    const float* ln1_g  = (const float*)d_in[5];
    const float* ln1_b  = (const float*)d_in[6];
    const float* ffn_W1 = (const float*)d_in[7];
    const float* ffn_b1 = (const float*)d_in[8];
    const float* ffn_W2 = (const float*)d_in[9];
    const float* ffn_b2 = (const float*)d_in[10];
    const float* ln2_g  = (const float*)d_in[11];
    const float* ln2_b  = (const float*)d_in[12];
    const float* out_W  = (const float*)d_in[13];
    const float* out_b  = (const float*)d_in[14];
    const float* d1_W   = (const float*)d_in[15];
    const float* d1_b   = (const float*)d_in[16];
    const float* bn1_g  = (const float*)d_in[17];
    const float* bn1_b  = (const float*)d_in[18];
    const float* bn1_m  = (const float*)d_in[19];
    const float* bn1_v  = (const float*)d_in[20];
    const float* d2_W   = (const float*)d_in[21];
    const float* d2_b   = (const float*)d_in[22];
    const float* bn2_g  = (const float*)d_in[23];
    const float* bn2_b  = (const float*)d_in[24];
    const float* bn2_m  = (const float*)d_in[25];
    const float* bn2_v  = (const float*)d_in[26];
    const float* fin_W  = (const float*)d_in[27];
    const float* fin_b  = (const float*)d_in[28];
    float* out = (float*)d_out;

    float *t, *o, *h;
    __half *t16, *qkv, *mid, *w1, *w2, *w3;
    cudaGetSymbolAddress((void**)&t,   g_t);
    cudaGetSymbolAddress((void**)&t16, g_t16);
    cudaGetSymbolAddress((void**)&qkv, g_qkv);
    cudaGetSymbolAddress((void**)&o,   g_o);
    cudaGetSymbolAddress((void**)&mid, g_mid);
    cudaGetSymbolAddress((void**)&h,   g_h);
    cudaGetSymbolAddress((void**)&w1,  g_w1);
    cudaGetSymbolAddress((void**)&w2,  g_w2);
    cudaGetSymbolAddress((void**)&w3,  g_w3);

    static int smem_set = 0;
    if (!smem_set) {
        cudaFuncSetAttribute(k_flash, cudaFuncAttributeMaxDynamicSharedMemorySize, FLASH_SMEM);
        cudaFuncSetAttribute(k_gemm_f16, cudaFuncAttributeMaxDynamicSharedMemorySize, GEMM_SMEM);
        smem_set = 1;
    }

    k_cvt16<<<(4 * 512 * 1536 + 255) / 256, 256>>>(qkv_W,  w1, 4 * 512 * 1536);
    k_cvt16<<<(4 * 512 * 2048 + 255) / 256, 256>>>(ffn_W1, w2, 4 * 512 * 2048);
    k_cvt16<<<(4 * 2048 * 512 + 255) / 256, 256>>>(ffn_W2, w3, 4 * 2048 * 512);

    k_inproj<<<65536, 256>>>(x, in_W, in_b, t, t16);

    for (int l = 0; l < 4; l++) {
        k_gemm_f16<<<dim3(12, 512), 256, GEMM_SMEM>>>(NROW, 1536, 512,
                                           t16, w1 + (size_t)l * 512 * 1536,
                                           qkv_b + l * 1536, qkv, 0, 1);
        k_flash<<<dim3(8, NBH), 256, FLASH_SMEM>>>(qkv, o);
        k_addln<<<NROW, 128>>>(t, o, ln1_g + l * 512, ln1_b + l * 512, t, t16);
        k_gemm_f16<<<dim3(16, 512), 256, GEMM_SMEM>>>(NROW, 2048, 512,
                                           t16, w2 + (size_t)l * 512 * 2048,
                                           ffn_b1 + l * 2048, mid, 1, 1);
        k_gemm_f16<<<dim3(4, 512), 256, GEMM_SMEM>>>(NROW, 512, 2048,
                                          mid, w3 + (size_t)l * 2048 * 512,
                                          ffn_b2 + l * 512, o, 0, 0);
        k_addln<<<NROW, 128>>>(t, o, ln2_g + l * 512, ln2_b + l * 512, t, t16);
    }

    k_outproj<<<8192, 256>>>(t, out_W, out_b, h);
    k_head<<<64, 256>>>(h, d1_W, d1_b, bn1_g, bn1_b, bn1_m, bn1_v,
                        d2_W, d2_b, bn2_g, bn2_b, bn2_m, bn2_v,
                        fin_W, fin_b, out);
}